// round 4
// baseline (speedup 1.0000x reference)
#include <cuda_runtime.h>
#include <cuda_bf16.h>
#include <math_constants.h>
#include <cstdint>

// Problem constants
#define Bc   32
#define Sc   511
#define Tc   512
#define Dc   512
#define Hc   8
#define HDc  64
#define Lc   4
#define PDc  32
#define FDc  448     // D - 2*PD
#define DFFc 2048
#define Mc   (Bc*Tc) // 16384 tokens

// ---------------- scratch (device globals; no allocation allowed) ----------
__device__ float g_x  [Mc*Dc];
__device__ float g_q  [Mc*Dc];
__device__ float g_k  [Mc*Dc];
__device__ float g_v  [Mc*Dc];
__device__ float g_att[Mc*Dc];
__device__ float g_tmp[Mc*Dc];
__device__ float g_ff [Mc*DFFc];

// ---------------- embedding + positional encoding ---------------------------
__global__ void embed_kernel(const float* __restrict__ runs,
                             const float* __restrict__ wickets,
                             const float* __restrict__ overs,
                             const int*   __restrict__ batters,
                             const int*   __restrict__ bowlers,
                             const float* __restrict__ pemb,
                             const float* __restrict__ Wf,
                             const float* __restrict__ bf,
                             const float* __restrict__ qtok,
                             float* __restrict__ x)
{
    int bt = blockIdx.x;
    int b  = bt / Tc;
    int t  = bt % Tc;
    int j  = threadIdx.x; // 0..511

    float val;
    if (t < Sc) {
        if (j < FDc) {
            float r = runs   [b*Sc + t];
            float w = wickets[b*Sc + t];
            float o = overs  [b*Sc + t];
            val = r*Wf[j] + w*Wf[FDc + j] + o*Wf[2*FDc + j] + bf[j];
        } else if (j < FDc + PDc) {
            val = pemb[batters[b*Sc + t]*PDc + (j - FDc)];
        } else {
            val = pemb[bowlers[b*Sc + t]*PDc + (j - FDc - PDc)];
        }
    } else {
        val = qtok[j];
    }
    int   i2  = j & ~1;
    float dv  = expf((float)i2 * -0.0179889460390111f); // ln(10000)/512
    float ang = (float)t * dv;
    val += (j & 1) ? cosf(ang) : sinf(ang);
    x[(b*Tc + t)*Dc + j] = val;
}

// ---------------- tf32 tensor-core GEMM (mma.sync), 3-stage cp.async ---------
#define TBM 128
#define TBN 128
#define TBK 32
#define AST 36
#define BST 136
#define TG_STAGES 3
#define TGEMM_SMEM ((TG_STAGES*TBM*AST + TG_STAGES*32*BST)*4)

__device__ __forceinline__ uint32_t smem_u32(const void* p) {
    return (uint32_t)__cvta_generic_to_shared(p);
}

__device__ __forceinline__ void tg_load_stage(
    const float* __restrict__ A, const float* __restrict__ W,
    float* __restrict__ As, float* __restrict__ Bs,
    int bm, int bn, int k0, int K, int N, int tid)
{
    int ar = tid >> 3, aq = tid & 7;
    const float* ap = A + (size_t)(bm*TBM + ar)*K + k0 + aq*4;
    uint32_t ad = smem_u32(As + ar*AST + aq*4);
    #pragma unroll
    for (int i = 0; i < 4; i++) {
        asm volatile("cp.async.cg.shared.global [%0], [%1], 16;\n"
                     :: "r"(ad + i*32*AST*4), "l"(ap + (size_t)i*32*K));
    }
    int br = tid >> 5, bq = tid & 31;
    const float* bp = W + (size_t)(k0 + br)*N + bn*TBN + bq*4;
    uint32_t bd = smem_u32(Bs + br*BST + bq*4);
    #pragma unroll
    for (int i = 0; i < 4; i++) {
        asm volatile("cp.async.cg.shared.global [%0], [%1], 16;\n"
                     :: "r"(bd + i*8*BST*4), "l"(bp + (size_t)i*8*N));
    }
    asm volatile("cp.async.commit_group;\n");
}

template<int EPI>
__global__ __launch_bounds__(256, 2)
void tgemm_kernel(const float* __restrict__ A, const float* __restrict__ W,
                  const float* __restrict__ bias, float* __restrict__ C,
                  int M, int N, int K)
{
    extern __shared__ float sm[];
    float* As = sm;                             // [3][128*AST]
    float* Bs = sm + TG_STAGES*TBM*AST;         // [3][32*BST]

    int tid = threadIdx.x;
    int bm = blockIdx.y, bn = blockIdx.x;
    int w = tid >> 5, lane = tid & 31;
    int gid = lane >> 2, tig = lane & 3;
    int wm = w >> 2, wn = w & 3;

    float acc[4][4][4];
    #pragma unroll
    for (int i = 0; i < 4; i++)
        #pragma unroll
        for (int j = 0; j < 4; j++)
            #pragma unroll
            for (int r = 0; r < 4; r++) acc[i][j][r] = 0.f;

    int nkt = K / TBK;
    tg_load_stage(A, W, As, Bs, bm, bn, 0, K, N, tid);
    tg_load_stage(A, W, As + TBM*AST, Bs + 32*BST, bm, bn, TBK, K, N, tid);

    for (int kt = 0; kt < nkt; ++kt) {
        int cur = kt % TG_STAGES;
        if (kt + 2 < nkt) {
            int nxt = (kt + 2) % TG_STAGES;
            tg_load_stage(A, W, As + nxt*TBM*AST, Bs + nxt*32*BST,
                          bm, bn, (kt+2)*TBK, K, N, tid);
            asm volatile("cp.async.wait_group 2;\n");
        } else if (kt + 1 < nkt) {
            asm volatile("cp.async.wait_group 1;\n");
        } else {
            asm volatile("cp.async.wait_group 0;\n");
        }
        __syncthreads();

        const float* Asc = As + cur*TBM*AST;
        const float* Bsc = Bs + cur*32*BST;

        #pragma unroll
        for (int kc = 0; kc < 4; ++kc) {
            uint32_t a[4][4], b[4][2];
            #pragma unroll
            for (int i = 0; i < 4; i++) {
                int r0 = wm*64 + 16*i + gid;
                a[i][0] = __float_as_uint(Asc[(r0    )*AST + kc*8 + tig    ]);
                a[i][1] = __float_as_uint(Asc[(r0 + 8)*AST + kc*8 + tig    ]);
                a[i][2] = __float_as_uint(Asc[(r0    )*AST + kc*8 + tig + 4]);
                a[i][3] = __float_as_uint(Asc[(r0 + 8)*AST + kc*8 + tig + 4]);
            }
            #pragma unroll
            for (int j = 0; j < 4; j++) {
                int c0 = wn*32 + 8*j + gid;
                b[j][0] = __float_as_uint(Bsc[(kc*8 + tig    )*BST + c0]);
                b[j][1] = __float_as_uint(Bsc[(kc*8 + tig + 4)*BST + c0]);
            }
            #pragma unroll
            for (int i = 0; i < 4; i++)
                #pragma unroll
                for (int j = 0; j < 4; j++) {
                    asm volatile(
                        "mma.sync.aligned.m16n8k8.row.col.f32.tf32.tf32.f32 "
                        "{%0,%1,%2,%3}, {%4,%5,%6,%7}, {%8,%9}, {%0,%1,%2,%3};\n"
                        : "+f"(acc[i][j][0]), "+f"(acc[i][j][1]),
                          "+f"(acc[i][j][2]), "+f"(acc[i][j][3])
                        : "r"(a[i][0]), "r"(a[i][1]), "r"(a[i][2]), "r"(a[i][3]),
                          "r"(b[j][0]), "r"(b[j][1]));
                }
        }
        __syncthreads();
    }

    #pragma unroll
    for (int i = 0; i < 4; i++) {
        int r = bm*TBM + wm*64 + 16*i + gid;
        #pragma unroll
        for (int j = 0; j < 4; j++) {
            int c = bn*TBN + wn*32 + 8*j + 2*tig;
            float bx = bias[c], by = bias[c+1];
            float v0 = acc[i][j][0] + bx;
            float v1 = acc[i][j][1] + by;
            float v2 = acc[i][j][2] + bx;
            float v3 = acc[i][j][3] + by;
            if (EPI == 1) {
                v0 = 0.5f*v0*(1.0f + erff(v0*0.70710678118654752f));
                v1 = 0.5f*v1*(1.0f + erff(v1*0.70710678118654752f));
                v2 = 0.5f*v2*(1.0f + erff(v2*0.70710678118654752f));
                v3 = 0.5f*v3*(1.0f + erff(v3*0.70710678118654752f));
            }
            float2 p0; p0.x = v0; p0.y = v1;
            float2 p1; p1.x = v2; p1.y = v3;
            *(float2*)&C[(size_t)r*N + c]       = p0;
            *(float2*)&C[(size_t)(r+8)*N + c]   = p1;
        }
    }
}

// ---------------- fused attention v2 -----------------------------------------
// 64 q-rows per block. grid (8, H, B), 256 threads. fp32 throughout.
// Smem: Qs[64d][68q] transposed, KV[64][68] (K transposed / V natural),
//       Sb[64 rows][516] scores, player ids.
#define AP 516
#define ATTN2_SMEM ((64*68 + 64*68 + 64*AP)*4 + 256*4)

__global__ __launch_bounds__(256)
void attn2_kernel(const float* __restrict__ Q, const float* __restrict__ Kg,
                  const float* __restrict__ Vg,
                  const int* __restrict__ batters, const int* __restrict__ bowlers,
                  const float* __restrict__ rec_s, const float* __restrict__ bow_s,
                  const float* __restrict__ bat_s, int layer,
                  float* __restrict__ Og)
{
    extern __shared__ float sm[];
    float* Qs = sm;              // [64][68] d-major (transposed)
    float* KV = Qs + 64*68;      // K transposed [d][k] / V natural [k][d], pitch 68
    float* Sb = KV + 64*68;      // [64][AP]
    int*   ib = (int*)(Sb + 64*AP);
    int* bowQ = ib;        int* batQ = ib + 64;
    int* bowK = ib + 128;  int* batK = ib + 192;

    int qt = blockIdx.x, h = blockIdx.y, b = blockIdx.z;
    int tid = threadIdx.x;
    int q0 = qt*64;
    int tq = tid >> 4, tk = tid & 15;   // 16 x 16 thread grid, 4x4 tiles

    // Q tile transposed
    for (int idx = tid; idx < 64*64; idx += 256) {
        int q = idx >> 6, d = idx & 63;
        Qs[d*68 + q] = Q[(size_t)(b*Tc + q0 + q)*Dc + h*HDc + d];
    }
    if (tid < 64) {
        int qg = q0 + tid;
        bowQ[tid] = (qg < Sc) ? bowlers[b*Sc + qg] : -1;
        batQ[tid] = (qg < Sc) ? batters[b*Sc + qg] : -1;
    }
    __syncthreads();

    int ktmax = qt + 1;
    int len   = ktmax*64;
    const float scl  = 0.125f;
    const float recw = rec_s[layer];
    const float boww = bow_s[layer];
    const float batw = bat_s[layer];

    // ---- scores ----
    for (int kt = 0; kt < ktmax; ++kt) {
        int k0 = kt*64;
        for (int idx = tid; idx < 64*64; idx += 256) {
            int kk = idx >> 6, d = idx & 63;
            KV[d*68 + kk] = Kg[(size_t)(b*Tc + k0 + kk)*Dc + h*HDc + d];
        }
        if (tid < 64) {
            int kg = k0 + tid;
            bowK[tid] = (kg < Sc) ? bowlers[b*Sc + kg] : -2;
            batK[tid] = (kg < Sc) ? batters[b*Sc + kg] : -2;
        }
        __syncthreads();

        float acc[4][4];
        #pragma unroll
        for (int i = 0; i < 4; i++)
            #pragma unroll
            for (int j = 0; j < 4; j++) acc[i][j] = 0.f;

        #pragma unroll 8
        for (int d = 0; d < 64; ++d) {
            float4 qv = *(const float4*)&Qs[d*68 + tq*4];
            float4 kv = *(const float4*)&KV[d*68 + tk*4];
            acc[0][0] += qv.x*kv.x; acc[0][1] += qv.x*kv.y; acc[0][2] += qv.x*kv.z; acc[0][3] += qv.x*kv.w;
            acc[1][0] += qv.y*kv.x; acc[1][1] += qv.y*kv.y; acc[1][2] += qv.y*kv.z; acc[1][3] += qv.y*kv.w;
            acc[2][0] += qv.z*kv.x; acc[2][1] += qv.z*kv.y; acc[2][2] += qv.z*kv.z; acc[2][3] += qv.z*kv.w;
            acc[3][0] += qv.w*kv.x; acc[3][1] += qv.w*kv.y; acc[3][2] += qv.w*kv.z; acc[3][3] += qv.w*kv.w;
        }

        #pragma unroll
        for (int i = 0; i < 4; ++i) {
            int ql = tq*4 + i;
            int qg = q0 + ql;
            int bq_ = bowQ[ql], aq_ = batQ[ql];
            #pragma unroll
            for (int j = 0; j < 4; ++j) {
                int kl = tk*4 + j;
                int kg = k0 + kl;
                float s = acc[i][j]*scl;
                if (h == 0)      s += recw * (float)kg * (1.0f/512.0f);
                else if (h == 1) { if (qg == Sc || kg == Sc || bq_ == bowK[kl]) s += boww; }
                else if (h == 2) { if (qg == Sc || kg == Sc || aq_ == batK[kl]) s += batw; }
                if (kg > qg) s = -CUDART_INF_F;
                Sb[ql*AP + kg] = s;
            }
        }
        __syncthreads();
    }

    // ---- softmax: warp w owns rows w*8..w*8+7, 3 passes, no local arrays ----
    int w = tid >> 5, lane = tid & 31;
    for (int r = w*8; r < w*8 + 8; ++r) {
        float* row = Sb + r*AP;
        float m = -CUDART_INF_F;
        for (int c = lane; c < len; c += 32) m = fmaxf(m, row[c]);
        #pragma unroll
        for (int o = 16; o; o >>= 1) m = fmaxf(m, __shfl_xor_sync(0xffffffffu, m, o));
        float ssum = 0.f;
        for (int c = lane; c < len; c += 32) {
            float e = expf(row[c] - m);
            row[c] = e;
            ssum += e;
        }
        #pragma unroll
        for (int o = 16; o; o >>= 1) ssum += __shfl_xor_sync(0xffffffffu, ssum, o);
        float inv = 1.0f/ssum;
        for (int c = lane; c < len; c += 32) row[c] *= inv;
    }
    __syncthreads();

    // ---- AV: thread tile 4q x 4d ----
    float o4[4][4];
    #pragma unroll
    for (int i = 0; i < 4; i++)
        #pragma unroll
        for (int j = 0; j < 4; j++) o4[i][j] = 0.f;

    for (int kt = 0; kt < ktmax; ++kt) {
        int k0 = kt*64;
        for (int idx = tid; idx < 64*64; idx += 256) {
            int kk = idx >> 6, d = idx & 63;
            KV[kk*68 + d] = Vg[(size_t)(b*Tc + k0 + kk)*Dc + h*HDc + d];
        }
        __syncthreads();
        const float* r0 = Sb + (tq*4+0)*AP + k0;
        const float* r1 = Sb + (tq*4+1)*AP + k0;
        const float* r2 = Sb + (tq*4+2)*AP + k0;
        const float* r3 = Sb + (tq*4+3)*AP + k0;
        #pragma unroll 8
        for (int kk = 0; kk < 64; ++kk) {
            float4 vv = *(const float4*)&KV[kk*68 + tk*4];
            float p0 = r0[kk], p1 = r1[kk], p2 = r2[kk], p3 = r3[kk];
            o4[0][0] += p0*vv.x; o4[0][1] += p0*vv.y; o4[0][2] += p0*vv.z; o4[0][3] += p0*vv.w;
            o4[1][0] += p1*vv.x; o4[1][1] += p1*vv.y; o4[1][2] += p1*vv.z; o4[1][3] += p1*vv.w;
            o4[2][0] += p2*vv.x; o4[2][1] += p2*vv.y; o4[2][2] += p2*vv.z; o4[2][3] += p2*vv.w;
            o4[3][0] += p3*vv.x; o4[3][1] += p3*vv.y; o4[3][2] += p3*vv.z; o4[3][3] += p3*vv.w;
        }
        __syncthreads();
    }
    #pragma unroll
    for (int i = 0; i < 4; ++i) {
        float4 ov; ov.x = o4[i][0]; ov.y = o4[i][1]; ov.z = o4[i][2]; ov.w = o4[i][3];
        *(float4*)&Og[(size_t)(b*Tc + q0 + tq*4 + i)*Dc + h*HDc + tk*4] = ov;
    }
}

// ---------------- residual add + LayerNorm (in-place on x) ------------------
__global__ __launch_bounds__(512)
void add_ln_kernel(float* __restrict__ x, const float* __restrict__ r,
                   const float* __restrict__ g, const float* __restrict__ be)
{
    int tok = blockIdx.x;
    int j = threadIdx.x;
    float v = x[(size_t)tok*Dc + j] + r[(size_t)tok*Dc + j];

    __shared__ float s1[16], s2[16];
    float a = v, b2 = v*v;
    #pragma unroll
    for (int o = 16; o; o >>= 1) {
        a  += __shfl_xor_sync(0xffffffffu, a, o);
        b2 += __shfl_xor_sync(0xffffffffu, b2, o);
    }
    int w = j >> 5, lane = j & 31;
    if (lane == 0) { s1[w] = a; s2[w] = b2; }
    __syncthreads();
    if (j < 16) {
        a = s1[j]; b2 = s2[j];
        #pragma unroll
        for (int o = 8; o; o >>= 1) {
            a  += __shfl_xor_sync(0x0000ffffu, a, o);
            b2 += __shfl_xor_sync(0x0000ffffu, b2, o);
        }
        if (j == 0) { s1[0] = a; s2[0] = b2; }
    }
    __syncthreads();
    float mu  = s1[0] * (1.0f/512.0f);
    float var = s2[0] * (1.0f/512.0f) - mu*mu;
    float y = (v - mu) * rsqrtf(var + 1e-5f) * g[j] + be[j];
    x[(size_t)tok*Dc + j] = y;
}

// ---------------- output head: out[b] = x[b, T-1] @ Wout + bout -------------
__global__ __launch_bounds__(512)
void out_kernel(const float* __restrict__ x, const float* __restrict__ Wout,
                const float* __restrict__ bout, float* __restrict__ out)
{
    int b = blockIdx.x;
    int n = threadIdx.x;
    __shared__ float xs[512];
    xs[n] = x[(size_t)(b*Tc + Tc - 1)*Dc + n];
    __syncthreads();
    float acc = bout[n];
    #pragma unroll 8
    for (int d = 0; d < Dc; ++d)
        acc += xs[d] * Wout[(size_t)d*Dc + n];
    out[b*Dc + n] = acc;
}

// ---------------- launcher ---------------------------------------------------
extern "C" void kernel_launch(void* const* d_in, const int* in_sizes, int n_in,
                              void* d_out, int out_size)
{
    const float* runs    = (const float*)d_in[0];
    const float* wickets = (const float*)d_in[1];
    const float* overs   = (const float*)d_in[2];
    const int*   batters = (const int*)  d_in[3];
    const int*   bowlers = (const int*)  d_in[4];
    const float* pemb    = (const float*)d_in[5];
    const float* Wf      = (const float*)d_in[6];
    const float* bf      = (const float*)d_in[7];
    const float* qtok    = (const float*)d_in[8];
    const float* Wq      = (const float*)d_in[9];
    const float* bq      = (const float*)d_in[10];
    const float* Wk      = (const float*)d_in[11];
    const float* bk      = (const float*)d_in[12];
    const float* Wv      = (const float*)d_in[13];
    const float* bv      = (const float*)d_in[14];
    const float* Wo      = (const float*)d_in[15];
    const float* bo      = (const float*)d_in[16];
    const float* rec_s   = (const float*)d_in[17];
    const float* bow_s   = (const float*)d_in[18];
    const float* bat_s   = (const float*)d_in[19];
    const float* W1      = (const float*)d_in[20];
    const float* b1      = (const float*)d_in[21];
    const float* W2      = (const float*)d_in[22];
    const float* b2      = (const float*)d_in[23];
    const float* g1      = (const float*)d_in[24];
    const float* be1     = (const float*)d_in[25];
    const float* g2      = (const float*)d_in[26];
    const float* be2     = (const float*)d_in[27];
    const float* Wout    = (const float*)d_in[28];
    const float* bout    = (const float*)d_in[29];
    float* out = (float*)d_out;

    float *x_, *q_, *k_, *v_, *att_, *tmp_, *ff_;
    cudaGetSymbolAddress((void**)&x_,   g_x);
    cudaGetSymbolAddress((void**)&q_,   g_q);
    cudaGetSymbolAddress((void**)&k_,   g_k);
    cudaGetSymbolAddress((void**)&v_,   g_v);
    cudaGetSymbolAddress((void**)&att_, g_att);
    cudaGetSymbolAddress((void**)&tmp_, g_tmp);
    cudaGetSymbolAddress((void**)&ff_,  g_ff);

    cudaFuncSetAttribute(attn2_kernel,
                         cudaFuncAttributeMaxDynamicSharedMemorySize, ATTN2_SMEM);
    cudaFuncSetAttribute(tgemm_kernel<0>,
                         cudaFuncAttributeMaxDynamicSharedMemorySize, TGEMM_SMEM);
    cudaFuncSetAttribute(tgemm_kernel<1>,
                         cudaFuncAttributeMaxDynamicSharedMemorySize, TGEMM_SMEM);

    embed_kernel<<<Bc*Tc, 512>>>(runs, wickets, overs, batters, bowlers,
                                 pemb, Wf, bf, qtok, x_);

    dim3 g512(Dc/TBN, Mc/TBM);     // (4, 128)
    dim3 g2048(DFFc/TBN, Mc/TBM);  // (16, 128)
    dim3 gattn(8, Hc, Bc);

    for (int l = 0; l < Lc; ++l) {
        const float* Wql = Wq + (size_t)l*Dc*Dc;
        const float* Wkl = Wk + (size_t)l*Dc*Dc;
        const float* Wvl = Wv + (size_t)l*Dc*Dc;
        const float* Wol = Wo + (size_t)l*Dc*Dc;

        tgemm_kernel<0><<<g512, 256, TGEMM_SMEM>>>(x_, Wql, bq + l*Dc, q_, Mc, Dc, Dc);
        tgemm_kernel<0><<<g512, 256, TGEMM_SMEM>>>(x_, Wkl, bk + l*Dc, k_, Mc, Dc, Dc);
        tgemm_kernel<0><<<g512, 256, TGEMM_SMEM>>>(x_, Wvl, bv + l*Dc, v_, Mc, Dc, Dc);

        attn2_kernel<<<gattn, 256, ATTN2_SMEM>>>(q_, k_, v_, batters, bowlers,
                                                 rec_s, bow_s, bat_s, l, att_);

        tgemm_kernel<0><<<g512, 256, TGEMM_SMEM>>>(att_, Wol, bo + l*Dc, tmp_, Mc, Dc, Dc);
        add_ln_kernel<<<Mc, 512>>>(x_, tmp_, g1 + l*Dc, be1 + l*Dc);

        tgemm_kernel<1><<<g2048, 256, TGEMM_SMEM>>>(x_, W1 + (size_t)l*Dc*DFFc, b1 + l*DFFc,
                                                    ff_, Mc, DFFc, Dc);
        tgemm_kernel<0><<<g512, 256, TGEMM_SMEM>>>(ff_, W2 + (size_t)l*DFFc*Dc, b2 + l*Dc,
                                                   tmp_, Mc, Dc, DFFc);
        add_ln_kernel<<<Mc, 512>>>(x_, tmp_, g2 + l*Dc, be2 + l*Dc);
    }

    out_kernel<<<Bc, 512>>>(x_, Wout, bout, out);
}

// round 5
// speedup vs baseline: 1.1220x; 1.1220x over previous
#include <cuda_runtime.h>
#include <cuda_bf16.h>
#include <math_constants.h>
#include <cstdint>

// Problem constants
#define Bc   32
#define Sc   511
#define Tc   512
#define Dc   512
#define Hc   8
#define HDc  64
#define Lc   4
#define PDc  32
#define FDc  448     // D - 2*PD
#define DFFc 2048
#define Mc   (Bc*Tc) // 16384 tokens

// ---------------- scratch (device globals; no allocation allowed) ----------
__device__ float g_x  [Mc*Dc];
__device__ float g_q  [Mc*Dc];
__device__ float g_k  [Mc*Dc];
__device__ float g_v  [Mc*Dc];
__device__ float g_att[Mc*Dc];
__device__ float g_tmp[Mc*Dc];
__device__ float g_ff [Mc*DFFc];

// ---------------- embedding + positional encoding ---------------------------
__global__ void embed_kernel(const float* __restrict__ runs,
                             const float* __restrict__ wickets,
                             const float* __restrict__ overs,
                             const int*   __restrict__ batters,
                             const int*   __restrict__ bowlers,
                             const float* __restrict__ pemb,
                             const float* __restrict__ Wf,
                             const float* __restrict__ bf,
                             const float* __restrict__ qtok,
                             float* __restrict__ x)
{
    int bt = blockIdx.x;
    int b  = bt / Tc;
    int t  = bt % Tc;
    int j  = threadIdx.x; // 0..511

    float val;
    if (t < Sc) {
        if (j < FDc) {
            float r = runs   [b*Sc + t];
            float w = wickets[b*Sc + t];
            float o = overs  [b*Sc + t];
            val = r*Wf[j] + w*Wf[FDc + j] + o*Wf[2*FDc + j] + bf[j];
        } else if (j < FDc + PDc) {
            val = pemb[batters[b*Sc + t]*PDc + (j - FDc)];
        } else {
            val = pemb[bowlers[b*Sc + t]*PDc + (j - FDc - PDc)];
        }
    } else {
        val = qtok[j];
    }
    int   i2  = j & ~1;
    float dv  = expf((float)i2 * -0.0179889460390111f); // ln(10000)/512
    float ang = (float)t * dv;
    val += (j & 1) ? cosf(ang) : sinf(ang);
    x[(b*Tc + t)*Dc + j] = val;
}

// ---------------- tf32 tensor-core GEMM (mma.sync), 2-stage cp.async ---------
#define TBM 128
#define TBN 128
#define TBK 32
#define AST 36
#define BST 136
#define TGEMM_SMEM ((2*TBM*AST + 2*32*BST)*4)

__device__ __forceinline__ uint32_t smem_u32(const void* p) {
    return (uint32_t)__cvta_generic_to_shared(p);
}

__device__ __forceinline__ void tg_load_stage(
    const float* __restrict__ A, const float* __restrict__ W,
    float* __restrict__ As, float* __restrict__ Bs,
    int bm, int bn, int k0, int K, int N, int tid)
{
    int ar = tid >> 3, aq = tid & 7;
    const float* ap = A + (size_t)(bm*TBM + ar)*K + k0 + aq*4;
    uint32_t ad = smem_u32(As + ar*AST + aq*4);
    #pragma unroll
    for (int i = 0; i < 4; i++) {
        asm volatile("cp.async.cg.shared.global [%0], [%1], 16;\n"
                     :: "r"(ad + i*32*AST*4), "l"(ap + (size_t)i*32*K));
    }
    int br = tid >> 5, bq = tid & 31;
    const float* bp = W + (size_t)(k0 + br)*N + bn*TBN + bq*4;
    uint32_t bd = smem_u32(Bs + br*BST + bq*4);
    #pragma unroll
    for (int i = 0; i < 4; i++) {
        asm volatile("cp.async.cg.shared.global [%0], [%1], 16;\n"
                     :: "r"(bd + i*8*BST*4), "l"(bp + (size_t)i*8*N));
    }
    asm volatile("cp.async.commit_group;\n");
}

template<int EPI>
__global__ __launch_bounds__(256, 2)
void tgemm_kernel(const float* __restrict__ A, const float* __restrict__ W,
                  const float* __restrict__ bias, float* __restrict__ C,
                  int M, int N, int K)
{
    extern __shared__ float sm[];
    float* As = sm;                       // [2][128*AST]
    float* Bs = sm + 2*TBM*AST;           // [2][32*BST]

    int tid = threadIdx.x;
    int bm = blockIdx.y, bn = blockIdx.x;
    int w = tid >> 5, lane = tid & 31;
    int gid = lane >> 2, tig = lane & 3;
    int wm = w >> 2, wn = w & 3;

    float acc[4][4][4];
    #pragma unroll
    for (int i = 0; i < 4; i++)
        #pragma unroll
        for (int j = 0; j < 4; j++)
            #pragma unroll
            for (int r = 0; r < 4; r++) acc[i][j][r] = 0.f;

    int nkt = K / TBK;
    tg_load_stage(A, W, As, Bs, bm, bn, 0, K, N, tid);

    for (int kt = 0; kt < nkt; ++kt) {
        int cur = kt & 1;
        if (kt + 1 < nkt) {
            tg_load_stage(A, W, As + (cur^1)*TBM*AST, Bs + (cur^1)*32*BST,
                          bm, bn, (kt+1)*TBK, K, N, tid);
            asm volatile("cp.async.wait_group 1;\n");
        } else {
            asm volatile("cp.async.wait_group 0;\n");
        }
        __syncthreads();

        const float* Asc = As + cur*TBM*AST;
        const float* Bsc = Bs + cur*32*BST;

        #pragma unroll
        for (int kc = 0; kc < 4; ++kc) {
            uint32_t a[4][4], b[4][2];
            #pragma unroll
            for (int i = 0; i < 4; i++) {
                int r0 = wm*64 + 16*i + gid;
                a[i][0] = __float_as_uint(Asc[(r0    )*AST + kc*8 + tig    ]);
                a[i][1] = __float_as_uint(Asc[(r0 + 8)*AST + kc*8 + tig    ]);
                a[i][2] = __float_as_uint(Asc[(r0    )*AST + kc*8 + tig + 4]);
                a[i][3] = __float_as_uint(Asc[(r0 + 8)*AST + kc*8 + tig + 4]);
            }
            #pragma unroll
            for (int j = 0; j < 4; j++) {
                int c0 = wn*32 + 8*j + gid;
                b[j][0] = __float_as_uint(Bsc[(kc*8 + tig    )*BST + c0]);
                b[j][1] = __float_as_uint(Bsc[(kc*8 + tig + 4)*BST + c0]);
            }
            #pragma unroll
            for (int i = 0; i < 4; i++)
                #pragma unroll
                for (int j = 0; j < 4; j++) {
                    asm volatile(
                        "mma.sync.aligned.m16n8k8.row.col.f32.tf32.tf32.f32 "
                        "{%0,%1,%2,%3}, {%4,%5,%6,%7}, {%8,%9}, {%0,%1,%2,%3};\n"
                        : "+f"(acc[i][j][0]), "+f"(acc[i][j][1]),
                          "+f"(acc[i][j][2]), "+f"(acc[i][j][3])
                        : "r"(a[i][0]), "r"(a[i][1]), "r"(a[i][2]), "r"(a[i][3]),
                          "r"(b[j][0]), "r"(b[j][1]));
                }
        }
        __syncthreads();
    }

    #pragma unroll
    for (int i = 0; i < 4; i++) {
        int r = bm*TBM + wm*64 + 16*i + gid;
        #pragma unroll
        for (int j = 0; j < 4; j++) {
            int c = bn*TBN + wn*32 + 8*j + 2*tig;
            float bx = bias[c], by = bias[c+1];
            float v0 = acc[i][j][0] + bx;
            float v1 = acc[i][j][1] + by;
            float v2 = acc[i][j][2] + bx;
            float v3 = acc[i][j][3] + by;
            if (EPI == 1) {
                v0 = 0.5f*v0*(1.0f + erff(v0*0.70710678118654752f));
                v1 = 0.5f*v1*(1.0f + erff(v1*0.70710678118654752f));
                v2 = 0.5f*v2*(1.0f + erff(v2*0.70710678118654752f));
                v3 = 0.5f*v3*(1.0f + erff(v3*0.70710678118654752f));
            }
            float2 p0; p0.x = v0; p0.y = v1;
            float2 p1; p1.x = v2; p1.y = v3;
            *(float2*)&C[(size_t)r*N + c]       = p0;
            *(float2*)&C[(size_t)(r+8)*N + c]   = p1;
        }
    }
}

// ---------------- fused attention v3 -----------------------------------------
// 32 q-rows per block, grid (16, H, B), 256 threads, fp32.
// K processed in 128-wide chunks. Score phase: 8x32 thread grid, 4q x 4k tiles.
// AV phase: (2 k-halves) x 8 x 16, 4q x 4d tiles, partials combined via smem.
#define AP 516
// floats: Qst 64*36=2304 | KV max(64*132,128*68)=8704 | Sb 32*516=16512 | ids 320
#define ATTN3_SMEM ((2304 + 8704 + 32*AP)*4 + 320*4)

__global__ __launch_bounds__(256)
void attn3_kernel(const float* __restrict__ Q, const float* __restrict__ Kg,
                  const float* __restrict__ Vg,
                  const int* __restrict__ batters, const int* __restrict__ bowlers,
                  const float* __restrict__ rec_s, const float* __restrict__ bow_s,
                  const float* __restrict__ bat_s, int layer,
                  float* __restrict__ Og)
{
    extern __shared__ float sm[];
    float* Qst = sm;                 // [64][36] Q transposed (d-major)
    float* KV  = sm + 2304;          // Kt [64][132] / V [128][68]
    float* Sb  = sm + 2304 + 8704;   // [32][516]
    int*   ib  = (int*)(Sb + 32*AP);
    int* bowQ = ib;        int* batQ = ib + 32;
    int* bowK = ib + 64;   int* batK = ib + 192;  // 128 each

    int qt = blockIdx.x, h = blockIdx.y, b = blockIdx.z;
    int tid = threadIdx.x;
    int q0 = qt*32;

    // load Q tile transposed
    for (int idx = tid; idx < 32*64; idx += 256) {
        int q = idx >> 6, d = idx & 63;
        Qst[d*36 + q] = Q[(size_t)(b*Tc + q0 + q)*Dc + h*HDc + d];
    }
    if (tid < 32) {
        int qg = q0 + tid;
        bowQ[tid] = (qg < Sc) ? bowlers[b*Sc + qg] : -1;
        batQ[tid] = (qg < Sc) ? batters[b*Sc + qg] : -1;
    }
    __syncthreads();

    int ktmax = (q0 + 32 + 127) >> 7;   // 128-wide chunks
    int len   = ktmax << 7;

    const float scl  = 0.125f;
    const float recw = rec_s[layer];
    const float boww = bow_s[layer];
    const float batw = bat_s[layer];

    // ---- scores: thread (tqs, tks) = 4 q rows x 4 k cols ----
    int tqs = tid >> 5;     // 0..7  (constant within warp -> Q loads broadcast)
    int tks = tid & 31;     // 0..31

    for (int kt = 0; kt < ktmax; ++kt) {
        int k0 = kt << 7;
        for (int idx = tid; idx < 128*64; idx += 256) {
            int kk = idx >> 6, d = idx & 63;
            KV[d*132 + kk] = Kg[(size_t)(b*Tc + k0 + kk)*Dc + h*HDc + d];
        }
        if (tid < 128) {
            int kg = k0 + tid;
            bowK[tid] = (kg < Sc) ? bowlers[b*Sc + kg] : -2;
            batK[tid] = (kg < Sc) ? batters[b*Sc + kg] : -2;
        }
        __syncthreads();

        float acc[4][4];
        #pragma unroll
        for (int i = 0; i < 4; i++)
            #pragma unroll
            for (int j = 0; j < 4; j++) acc[i][j] = 0.f;

        #pragma unroll 8
        for (int d = 0; d < 64; ++d) {
            float4 qv = *(const float4*)&Qst[d*36 + tqs*4];
            float4 kv = *(const float4*)&KV[d*132 + tks*4];
            acc[0][0] += qv.x*kv.x; acc[0][1] += qv.x*kv.y; acc[0][2] += qv.x*kv.z; acc[0][3] += qv.x*kv.w;
            acc[1][0] += qv.y*kv.x; acc[1][1] += qv.y*kv.y; acc[1][2] += qv.y*kv.z; acc[1][3] += qv.y*kv.w;
            acc[2][0] += qv.z*kv.x; acc[2][1] += qv.z*kv.y; acc[2][2] += qv.z*kv.z; acc[2][3] += qv.z*kv.w;
            acc[3][0] += qv.w*kv.x; acc[3][1] += qv.w*kv.y; acc[3][2] += qv.w*kv.z; acc[3][3] += qv.w*kv.w;
        }

        #pragma unroll
        for (int i = 0; i < 4; ++i) {
            int ql = tqs*4 + i;
            int qg = q0 + ql;
            int bq_ = bowQ[ql], aq_ = batQ[ql];
            float sv[4];
            #pragma unroll
            for (int j = 0; j < 4; ++j) {
                int kl = tks*4 + j;
                int kg = k0 + kl;
                float s = acc[i][j]*scl;
                if (h == 0)      s += recw * (float)kg * (1.0f/512.0f);
                else if (h == 1) { if (qg == Sc || kg == Sc || bq_ == bowK[kl]) s += boww; }
                else if (h == 2) { if (qg == Sc || kg == Sc || aq_ == batK[kl]) s += batw; }
                if (kg > qg) s = -CUDART_INF_F;
                sv[j] = s;
            }
            float4 svv; svv.x = sv[0]; svv.y = sv[1]; svv.z = sv[2]; svv.w = sv[3];
            *(float4*)&Sb[ql*AP + k0 + tks*4] = svv;
        }
        __syncthreads();
    }

    // ---- softmax: warp w owns rows w*4..w*4+3, 3 passes, no local arrays ----
    int w = tid >> 5, lane = tid & 31;
    for (int r = w*4; r < w*4 + 4; ++r) {
        float* row = Sb + r*AP;
        float m = -CUDART_INF_F;
        for (int c = lane; c < len; c += 32) m = fmaxf(m, row[c]);
        #pragma unroll
        for (int o = 16; o; o >>= 1) m = fmaxf(m, __shfl_xor_sync(0xffffffffu, m, o));
        float ssum = 0.f;
        for (int c = lane; c < len; c += 32) {
            float e = expf(row[c] - m);
            row[c] = e;
            ssum += e;
        }
        #pragma unroll
        for (int o = 16; o; o >>= 1) ssum += __shfl_xor_sync(0xffffffffu, ssum, o);
        float inv = 1.0f/ssum;
        for (int c = lane; c < len; c += 32) row[c] *= inv;
    }
    __syncthreads();

    // ---- AV: thread (ks, tqa, tda) = 4q x 4d over half the kk range ----
    int ks  = tid >> 7;            // 0/1 k-half
    int rem = tid & 127;
    int tqa = rem >> 4;            // 0..7
    int tda = rem & 15;            // 0..15

    float o4[4][4];
    #pragma unroll
    for (int i = 0; i < 4; i++)
        #pragma unroll
        for (int j = 0; j < 4; j++) o4[i][j] = 0.f;

    for (int kt = 0; kt < ktmax; ++kt) {
        int k0 = kt << 7;
        for (int idx = tid; idx < 128*64; idx += 256) {
            int kk = idx >> 6, d = idx & 63;
            KV[kk*68 + d] = Vg[(size_t)(b*Tc + k0 + kk)*Dc + h*HDc + d];
        }
        __syncthreads();
        int kb = ks*64;
        const float* r0 = Sb + (tqa*4+0)*AP + k0 + kb;
        const float* r1 = Sb + (tqa*4+1)*AP + k0 + kb;
        const float* r2 = Sb + (tqa*4+2)*AP + k0 + kb;
        const float* r3 = Sb + (tqa*4+3)*AP + k0 + kb;
        const float* vb = KV + kb*68 + tda*4;
        #pragma unroll 8
        for (int kk = 0; kk < 64; ++kk) {
            float4 vv = *(const float4*)(vb + kk*68);
            float p0 = r0[kk], p1 = r1[kk], p2 = r2[kk], p3 = r3[kk];
            o4[0][0] += p0*vv.x; o4[0][1] += p0*vv.y; o4[0][2] += p0*vv.z; o4[0][3] += p0*vv.w;
            o4[1][0] += p1*vv.x; o4[1][1] += p1*vv.y; o4[1][2] += p1*vv.z; o4[1][3] += p1*vv.w;
            o4[2][0] += p2*vv.x; o4[2][1] += p2*vv.y; o4[2][2] += p2*vv.z; o4[2][3] += p2*vv.w;
            o4[3][0] += p3*vv.x; o4[3][1] += p3*vv.y; o4[3][2] += p3*vv.z; o4[3][3] += p3*vv.w;
        }
        __syncthreads();
    }

    // combine k-halves via smem (reuse Qst region: 32*64 = 2048 floats <= 2304)
    float* Pb = Qst;
    if (ks == 1) {
        #pragma unroll
        for (int i = 0; i < 4; ++i) {
            float4 pv; pv.x = o4[i][0]; pv.y = o4[i][1]; pv.z = o4[i][2]; pv.w = o4[i][3];
            *(float4*)&Pb[(tqa*4+i)*64 + tda*4] = pv;
        }
    }
    __syncthreads();
    if (ks == 0) {
        #pragma unroll
        for (int i = 0; i < 4; ++i) {
            float4 pv = *(const float4*)&Pb[(tqa*4+i)*64 + tda*4];
            float4 ov;
            ov.x = o4[i][0] + pv.x;
            ov.y = o4[i][1] + pv.y;
            ov.z = o4[i][2] + pv.z;
            ov.w = o4[i][3] + pv.w;
            *(float4*)&Og[(size_t)(b*Tc + q0 + tqa*4 + i)*Dc + h*HDc + tda*4] = ov;
        }
    }
}

// ---------------- residual add + LayerNorm (in-place on x) ------------------
__global__ __launch_bounds__(512)
void add_ln_kernel(float* __restrict__ x, const float* __restrict__ r,
                   const float* __restrict__ g, const float* __restrict__ be)
{
    int tok = blockIdx.x;
    int j = threadIdx.x;
    float v = x[(size_t)tok*Dc + j] + r[(size_t)tok*Dc + j];

    __shared__ float s1[16], s2[16];
    float a = v, b2 = v*v;
    #pragma unroll
    for (int o = 16; o; o >>= 1) {
        a  += __shfl_xor_sync(0xffffffffu, a, o);
        b2 += __shfl_xor_sync(0xffffffffu, b2, o);
    }
    int w = j >> 5, lane = j & 31;
    if (lane == 0) { s1[w] = a; s2[w] = b2; }
    __syncthreads();
    if (j < 16) {
        a = s1[j]; b2 = s2[j];
        #pragma unroll
        for (int o = 8; o; o >>= 1) {
            a  += __shfl_xor_sync(0x0000ffffu, a, o);
            b2 += __shfl_xor_sync(0x0000ffffu, b2, o);
        }
        if (j == 0) { s1[0] = a; s2[0] = b2; }
    }
    __syncthreads();
    float mu  = s1[0] * (1.0f/512.0f);
    float var = s2[0] * (1.0f/512.0f) - mu*mu;
    float y = (v - mu) * rsqrtf(var + 1e-5f) * g[j] + be[j];
    x[(size_t)tok*Dc + j] = y;
}

// ---------------- output head: out[b] = x[b, T-1] @ Wout + bout -------------
__global__ __launch_bounds__(512)
void out_kernel(const float* __restrict__ x, const float* __restrict__ Wout,
                const float* __restrict__ bout, float* __restrict__ out)
{
    int b = blockIdx.x;
    int n = threadIdx.x;
    __shared__ float xs[512];
    xs[n] = x[(size_t)(b*Tc + Tc - 1)*Dc + n];
    __syncthreads();
    float acc = bout[n];
    #pragma unroll 8
    for (int d = 0; d < Dc; ++d)
        acc += xs[d] * Wout[(size_t)d*Dc + n];
    out[b*Dc + n] = acc;
}

// ---------------- launcher ---------------------------------------------------
extern "C" void kernel_launch(void* const* d_in, const int* in_sizes, int n_in,
                              void* d_out, int out_size)
{
    const float* runs    = (const float*)d_in[0];
    const float* wickets = (const float*)d_in[1];
    const float* overs   = (const float*)d_in[2];
    const int*   batters = (const int*)  d_in[3];
    const int*   bowlers = (const int*)  d_in[4];
    const float* pemb    = (const float*)d_in[5];
    const float* Wf      = (const float*)d_in[6];
    const float* bf      = (const float*)d_in[7];
    const float* qtok    = (const float*)d_in[8];
    const float* Wq      = (const float*)d_in[9];
    const float* bq      = (const float*)d_in[10];
    const float* Wk      = (const float*)d_in[11];
    const float* bk      = (const float*)d_in[12];
    const float* Wv      = (const float*)d_in[13];
    const float* bv      = (const float*)d_in[14];
    const float* Wo      = (const float*)d_in[15];
    const float* bo      = (const float*)d_in[16];
    const float* rec_s   = (const float*)d_in[17];
    const float* bow_s   = (const float*)d_in[18];
    const float* bat_s   = (const float*)d_in[19];
    const float* W1      = (const float*)d_in[20];
    const float* b1      = (const float*)d_in[21];
    const float* W2      = (const float*)d_in[22];
    const float* b2      = (const float*)d_in[23];
    const float* g1      = (const float*)d_in[24];
    const float* be1     = (const float*)d_in[25];
    const float* g2      = (const float*)d_in[26];
    const float* be2     = (const float*)d_in[27];
    const float* Wout    = (const float*)d_in[28];
    const float* bout    = (const float*)d_in[29];
    float* out = (float*)d_out;

    float *x_, *q_, *k_, *v_, *att_, *tmp_, *ff_;
    cudaGetSymbolAddress((void**)&x_,   g_x);
    cudaGetSymbolAddress((void**)&q_,   g_q);
    cudaGetSymbolAddress((void**)&k_,   g_k);
    cudaGetSymbolAddress((void**)&v_,   g_v);
    cudaGetSymbolAddress((void**)&att_, g_att);
    cudaGetSymbolAddress((void**)&tmp_, g_tmp);
    cudaGetSymbolAddress((void**)&ff_,  g_ff);

    cudaFuncSetAttribute(attn3_kernel,
                         cudaFuncAttributeMaxDynamicSharedMemorySize, ATTN3_SMEM);
    cudaFuncSetAttribute(tgemm_kernel<0>,
                         cudaFuncAttributeMaxDynamicSharedMemorySize, TGEMM_SMEM);
    cudaFuncSetAttribute(tgemm_kernel<1>,
                         cudaFuncAttributeMaxDynamicSharedMemorySize, TGEMM_SMEM);

    embed_kernel<<<Bc*Tc, 512>>>(runs, wickets, overs, batters, bowlers,
                                 pemb, Wf, bf, qtok, x_);

    dim3 g512(Dc/TBN, Mc/TBM);     // (4, 128)
    dim3 g2048(DFFc/TBN, Mc/TBM);  // (16, 128)
    dim3 gattn(16, Hc, Bc);

    for (int l = 0; l < Lc; ++l) {
        const float* Wql = Wq + (size_t)l*Dc*Dc;
        const float* Wkl = Wk + (size_t)l*Dc*Dc;
        const float* Wvl = Wv + (size_t)l*Dc*Dc;
        const float* Wol = Wo + (size_t)l*Dc*Dc;

        tgemm_kernel<0><<<g512, 256, TGEMM_SMEM>>>(x_, Wql, bq + l*Dc, q_, Mc, Dc, Dc);
        tgemm_kernel<0><<<g512, 256, TGEMM_SMEM>>>(x_, Wkl, bk + l*Dc, k_, Mc, Dc, Dc);
        tgemm_kernel<0><<<g512, 256, TGEMM_SMEM>>>(x_, Wvl, bv + l*Dc, v_, Mc, Dc, Dc);

        attn3_kernel<<<gattn, 256, ATTN3_SMEM>>>(q_, k_, v_, batters, bowlers,
                                                 rec_s, bow_s, bat_s, l, att_);

        tgemm_kernel<0><<<g512, 256, TGEMM_SMEM>>>(att_, Wol, bo + l*Dc, tmp_, Mc, Dc, Dc);
        add_ln_kernel<<<Mc, 512>>>(x_, tmp_, g1 + l*Dc, be1 + l*Dc);

        tgemm_kernel<1><<<g2048, 256, TGEMM_SMEM>>>(x_, W1 + (size_t)l*Dc*DFFc, b1 + l*DFFc,
                                                    ff_, Mc, DFFc, Dc);
        tgemm_kernel<0><<<g512, 256, TGEMM_SMEM>>>(ff_, W2 + (size_t)l*DFFc*Dc, b2 + l*Dc,
                                                   tmp_, Mc, Dc, DFFc);
        add_ln_kernel<<<Mc, 512>>>(x_, tmp_, g2 + l*Dc, be2 + l*Dc);
    }

    out_kernel<<<Bc, 512>>>(x_, Wout, bout, out);
}

// round 6
// speedup vs baseline: 1.1490x; 1.0241x over previous
#include <cuda_runtime.h>
#include <cuda_bf16.h>
#include <math_constants.h>
#include <cstdint>

// Problem constants
#define Bc   32
#define Sc   511
#define Tc   512
#define Dc   512
#define Hc   8
#define HDc  64
#define Lc   4
#define PDc  32
#define FDc  448     // D - 2*PD
#define DFFc 2048
#define Mc   (Bc*Tc) // 16384 tokens
#define QP   1536    // qkv combined pitch

// ---------------- scratch (device globals; no allocation allowed) ----------
__device__ float g_x   [Mc*Dc];
__device__ float g_att [Mc*Dc];
__device__ float g_tmp [Mc*Dc];
__device__ float g_ff  [Mc*DFFc];      // doubles as qkv buffer [Mc][1536]
__device__ float g_wqkv[Lc*Dc*QP];
__device__ float g_bqkv[Lc*QP];

// ---------------- weight packing --------------------------------------------
__global__ __launch_bounds__(512)
void pack_qkv_kernel(const float* __restrict__ Wq, const float* __restrict__ Wk,
                     const float* __restrict__ Wv, float* __restrict__ Wqkv)
{
    int lk = blockIdx.x;            // l*512 + k, 0..Lc*Dc-1
    int j  = threadIdx.x;           // 0..511
    size_t src = (size_t)lk*Dc + j;
    size_t dst = (size_t)lk*QP + j;
    Wqkv[dst        ] = Wq[src];
    Wqkv[dst + Dc   ] = Wk[src];
    Wqkv[dst + 2*Dc ] = Wv[src];
}
__global__ __launch_bounds__(512)
void pack_bqkv_kernel(const float* __restrict__ bq, const float* __restrict__ bk,
                      const float* __restrict__ bv, float* __restrict__ bqkv)
{
    int l = blockIdx.x;
    int j = threadIdx.x;
    bqkv[l*QP + j       ] = bq[l*Dc + j];
    bqkv[l*QP + j + Dc  ] = bk[l*Dc + j];
    bqkv[l*QP + j + 2*Dc] = bv[l*Dc + j];
}

// ---------------- embedding + positional encoding ---------------------------
__global__ void embed_kernel(const float* __restrict__ runs,
                             const float* __restrict__ wickets,
                             const float* __restrict__ overs,
                             const int*   __restrict__ batters,
                             const int*   __restrict__ bowlers,
                             const float* __restrict__ pemb,
                             const float* __restrict__ Wf,
                             const float* __restrict__ bf,
                             const float* __restrict__ qtok,
                             float* __restrict__ x)
{
    int bt = blockIdx.x;
    int b  = bt / Tc;
    int t  = bt % Tc;
    int j  = threadIdx.x; // 0..511

    float val;
    if (t < Sc) {
        if (j < FDc) {
            float r = runs   [b*Sc + t];
            float w = wickets[b*Sc + t];
            float o = overs  [b*Sc + t];
            val = r*Wf[j] + w*Wf[FDc + j] + o*Wf[2*FDc + j] + bf[j];
        } else if (j < FDc + PDc) {
            val = pemb[batters[b*Sc + t]*PDc + (j - FDc)];
        } else {
            val = pemb[bowlers[b*Sc + t]*PDc + (j - FDc - PDc)];
        }
    } else {
        val = qtok[j];
    }
    int   i2  = j & ~1;
    float dv  = expf((float)i2 * -0.0179889460390111f); // ln(10000)/512
    float ang = (float)t * dv;
    val += (j & 1) ? cosf(ang) : sinf(ang);
    x[(b*Tc + t)*Dc + j] = val;
}

// ---------------- tf32 tensor-core GEMM (mma.sync), 2-stage cp.async ---------
#define TBM 128
#define TBN 128
#define TBK 32
#define AST 36
#define BST 136
#define TGEMM_SMEM ((2*TBM*AST + 2*32*BST)*4)

__device__ __forceinline__ uint32_t smem_u32(const void* p) {
    return (uint32_t)__cvta_generic_to_shared(p);
}

__device__ __forceinline__ void tg_load_stage(
    const float* __restrict__ A, const float* __restrict__ W,
    float* __restrict__ As, float* __restrict__ Bs,
    int bm, int bn, int k0, int K, int N, int tid)
{
    int ar = tid >> 3, aq = tid & 7;
    const float* ap = A + (size_t)(bm*TBM + ar)*K + k0 + aq*4;
    uint32_t ad = smem_u32(As + ar*AST + aq*4);
    #pragma unroll
    for (int i = 0; i < 4; i++) {
        asm volatile("cp.async.cg.shared.global [%0], [%1], 16;\n"
                     :: "r"(ad + i*32*AST*4), "l"(ap + (size_t)i*32*K));
    }
    int br = tid >> 5, bq = tid & 31;
    const float* bp = W + (size_t)(k0 + br)*N + bn*TBN + bq*4;
    uint32_t bd = smem_u32(Bs + br*BST + bq*4);
    #pragma unroll
    for (int i = 0; i < 4; i++) {
        asm volatile("cp.async.cg.shared.global [%0], [%1], 16;\n"
                     :: "r"(bd + i*8*BST*4), "l"(bp + (size_t)i*8*N));
    }
    asm volatile("cp.async.commit_group;\n");
}

template<int EPI>
__global__ __launch_bounds__(256, 2)
void tgemm_kernel(const float* __restrict__ A, const float* __restrict__ W,
                  const float* __restrict__ bias, float* __restrict__ C,
                  int M, int N, int K)
{
    extern __shared__ float sm[];
    float* As = sm;
    float* Bs = sm + 2*TBM*AST;

    int tid = threadIdx.x;
    int bm = blockIdx.y, bn = blockIdx.x;
    int w = tid >> 5, lane = tid & 31;
    int gid = lane >> 2, tig = lane & 3;
    int wm = w >> 2, wn = w & 3;

    float acc[4][4][4];
    #pragma unroll
    for (int i = 0; i < 4; i++)
        #pragma unroll
        for (int j = 0; j < 4; j++)
            #pragma unroll
            for (int r = 0; r < 4; r++) acc[i][j][r] = 0.f;

    int nkt = K / TBK;
    tg_load_stage(A, W, As, Bs, bm, bn, 0, K, N, tid);

    for (int kt = 0; kt < nkt; ++kt) {
        int cur = kt & 1;
        if (kt + 1 < nkt) {
            tg_load_stage(A, W, As + (cur^1)*TBM*AST, Bs + (cur^1)*32*BST,
                          bm, bn, (kt+1)*TBK, K, N, tid);
            asm volatile("cp.async.wait_group 1;\n");
        } else {
            asm volatile("cp.async.wait_group 0;\n");
        }
        __syncthreads();

        const float* Asc = As + cur*TBM*AST;
        const float* Bsc = Bs + cur*32*BST;

        #pragma unroll
        for (int kc = 0; kc < 4; ++kc) {
            uint32_t a[4][4], b[4][2];
            #pragma unroll
            for (int i = 0; i < 4; i++) {
                int r0 = wm*64 + 16*i + gid;
                a[i][0] = __float_as_uint(Asc[(r0    )*AST + kc*8 + tig    ]);
                a[i][1] = __float_as_uint(Asc[(r0 + 8)*AST + kc*8 + tig    ]);
                a[i][2] = __float_as_uint(Asc[(r0    )*AST + kc*8 + tig + 4]);
                a[i][3] = __float_as_uint(Asc[(r0 + 8)*AST + kc*8 + tig + 4]);
            }
            #pragma unroll
            for (int j = 0; j < 4; j++) {
                int c0 = wn*32 + 8*j + gid;
                b[j][0] = __float_as_uint(Bsc[(kc*8 + tig    )*BST + c0]);
                b[j][1] = __float_as_uint(Bsc[(kc*8 + tig + 4)*BST + c0]);
            }
            #pragma unroll
            for (int i = 0; i < 4; i++)
                #pragma unroll
                for (int j = 0; j < 4; j++) {
                    asm volatile(
                        "mma.sync.aligned.m16n8k8.row.col.f32.tf32.tf32.f32 "
                        "{%0,%1,%2,%3}, {%4,%5,%6,%7}, {%8,%9}, {%0,%1,%2,%3};\n"
                        : "+f"(acc[i][j][0]), "+f"(acc[i][j][1]),
                          "+f"(acc[i][j][2]), "+f"(acc[i][j][3])
                        : "r"(a[i][0]), "r"(a[i][1]), "r"(a[i][2]), "r"(a[i][3]),
                          "r"(b[j][0]), "r"(b[j][1]));
                }
        }
        __syncthreads();
    }

    #pragma unroll
    for (int i = 0; i < 4; i++) {
        int r = bm*TBM + wm*64 + 16*i + gid;
        #pragma unroll
        for (int j = 0; j < 4; j++) {
            int c = bn*TBN + wn*32 + 8*j + 2*tig;
            float bx = bias[c], by = bias[c+1];
            float v0 = acc[i][j][0] + bx;
            float v1 = acc[i][j][1] + by;
            float v2 = acc[i][j][2] + bx;
            float v3 = acc[i][j][3] + by;
            if (EPI == 1) {
                v0 = 0.5f*v0*(1.0f + erff(v0*0.70710678118654752f));
                v1 = 0.5f*v1*(1.0f + erff(v1*0.70710678118654752f));
                v2 = 0.5f*v2*(1.0f + erff(v2*0.70710678118654752f));
                v3 = 0.5f*v3*(1.0f + erff(v3*0.70710678118654752f));
            }
            float2 p0; p0.x = v0; p0.y = v1;
            float2 p1; p1.x = v2; p1.y = v3;
            *(float2*)&C[(size_t)r*N + c]       = p0;
            *(float2*)&C[(size_t)(r+8)*N + c]   = p1;
        }
    }
}

// ---------------- fused attention v4 -----------------------------------------
// 32 q-rows per block, grid (16, H, B), 256 threads, fp32.
// Reads combined qkv buffer (pitch QP). Row max tracked in registers during the
// score phase; normalization deferred to the final AV store (1/rowsum).
#define AP 516
#define ATTN4_SMEM ((2304 + 8704 + 32*AP)*4 + 320*4 + 32*4)

__global__ __launch_bounds__(256)
void attn4_kernel(const float* __restrict__ qkv,
                  const int* __restrict__ batters, const int* __restrict__ bowlers,
                  const float* __restrict__ rec_s, const float* __restrict__ bow_s,
                  const float* __restrict__ bat_s, int layer,
                  float* __restrict__ Og)
{
    extern __shared__ float sm[];
    float* Qst = sm;                 // [64][36] Q transposed; later Mp[32][32]/Pb[32][64]
    float* KV  = sm + 2304;          // Kt [64][132] / V [128][68]
    float* Sb  = sm + 2304 + 8704;   // [32][516]
    int*   ib  = (int*)(Sb + 32*AP);
    int* bowQ = ib;        int* batQ = ib + 32;
    int* bowK = ib + 64;   int* batK = ib + 192;  // 128 each
    float* Ssum = (float*)(ib + 320);              // [32]

    int qt = blockIdx.x, h = blockIdx.y, b = blockIdx.z;
    int tid = threadIdx.x;
    int q0 = qt*32;

    const float* Q  = qkv;
    const float* Kg = qkv + Dc;
    const float* Vg = qkv + 2*Dc;

    // load Q tile transposed
    for (int idx = tid; idx < 32*64; idx += 256) {
        int q = idx >> 6, d = idx & 63;
        Qst[d*36 + q] = Q[(size_t)(b*Tc + q0 + q)*QP + h*HDc + d];
    }
    if (tid < 32) {
        int qg = q0 + tid;
        bowQ[tid] = (qg < Sc) ? bowlers[b*Sc + qg] : -1;
        batQ[tid] = (qg < Sc) ? batters[b*Sc + qg] : -1;
    }
    __syncthreads();

    int ktmax = (q0 + 32 + 127) >> 7;
    int len   = ktmax << 7;

    const float scl  = 0.125f;
    const float recw = rec_s[layer];
    const float boww = bow_s[layer];
    const float batw = bat_s[layer];

    // ---- scores + register row-max ----
    int tqs = tid >> 5;     // 0..7
    int tks = tid & 31;     // 0..31
    float mreg[4] = {-CUDART_INF_F, -CUDART_INF_F, -CUDART_INF_F, -CUDART_INF_F};

    for (int kt = 0; kt < ktmax; ++kt) {
        int k0 = kt << 7;
        for (int idx = tid; idx < 128*64; idx += 256) {
            int kk = idx >> 6, d = idx & 63;
            KV[d*132 + kk] = Kg[(size_t)(b*Tc + k0 + kk)*QP + h*HDc + d];
        }
        if (tid < 128) {
            int kg = k0 + tid;
            bowK[tid] = (kg < Sc) ? bowlers[b*Sc + kg] : -2;
            batK[tid] = (kg < Sc) ? batters[b*Sc + kg] : -2;
        }
        __syncthreads();

        float acc[4][4];
        #pragma unroll
        for (int i = 0; i < 4; i++)
            #pragma unroll
            for (int j = 0; j < 4; j++) acc[i][j] = 0.f;

        #pragma unroll 8
        for (int d = 0; d < 64; ++d) {
            float4 qv = *(const float4*)&Qst[d*36 + tqs*4];
            float4 kv = *(const float4*)&KV[d*132 + tks*4];
            acc[0][0] += qv.x*kv.x; acc[0][1] += qv.x*kv.y; acc[0][2] += qv.x*kv.z; acc[0][3] += qv.x*kv.w;
            acc[1][0] += qv.y*kv.x; acc[1][1] += qv.y*kv.y; acc[1][2] += qv.y*kv.z; acc[1][3] += qv.y*kv.w;
            acc[2][0] += qv.z*kv.x; acc[2][1] += qv.z*kv.y; acc[2][2] += qv.z*kv.z; acc[2][3] += qv.z*kv.w;
            acc[3][0] += qv.w*kv.x; acc[3][1] += qv.w*kv.y; acc[3][2] += qv.w*kv.z; acc[3][3] += qv.w*kv.w;
        }

        #pragma unroll
        for (int i = 0; i < 4; ++i) {
            int ql = tqs*4 + i;
            int qg = q0 + ql;
            int bq_ = bowQ[ql], aq_ = batQ[ql];
            float sv[4];
            #pragma unroll
            for (int j = 0; j < 4; ++j) {
                int kl = tks*4 + j;
                int kg = k0 + kl;
                float s = acc[i][j]*scl;
                if (h == 0)      s += recw * (float)kg * (1.0f/512.0f);
                else if (h == 1) { if (qg == Sc || kg == Sc || bq_ == bowK[kl]) s += boww; }
                else if (h == 2) { if (qg == Sc || kg == Sc || aq_ == batK[kl]) s += batw; }
                if (kg > qg) s = -CUDART_INF_F;
                sv[j] = s;
                mreg[i] = fmaxf(mreg[i], s);
            }
            float4 svv; svv.x = sv[0]; svv.y = sv[1]; svv.z = sv[2]; svv.w = sv[3];
            *(float4*)&Sb[ql*AP + k0 + tks*4] = svv;
        }
        __syncthreads();
    }

    // ---- partial-max reduce (Mp in reused Qst area) ----
    float* Mp = Qst;   // [32][32]
    #pragma unroll
    for (int i = 0; i < 4; ++i)
        Mp[(tqs*4 + i)*32 + tks] = mreg[i];
    __syncthreads();

    // ---- exp + sum pass (single Sb pass), deferred normalization ----
    int w = tid >> 5, lane = tid & 31;
    for (int r = w*4; r < w*4 + 4; ++r) {
        float m = Mp[r*32 + lane];
        #pragma unroll
        for (int o = 16; o; o >>= 1) m = fmaxf(m, __shfl_xor_sync(0xffffffffu, m, o));
        float* row = Sb + r*AP;
        float ssum = 0.f;
        for (int c = lane; c < len; c += 32) {
            float e = __expf(row[c] - m);
            row[c] = e;
            ssum += e;
        }
        #pragma unroll
        for (int o = 16; o; o >>= 1) ssum += __shfl_xor_sync(0xffffffffu, ssum, o);
        if (lane == 0) Ssum[r] = ssum;
    }
    __syncthreads();

    // ---- AV: (2 k-halves) x 8q x 16d, 4q x 4d tiles, unnormalized ----
    int ks  = tid >> 7;
    int rem = tid & 127;
    int tqa = rem >> 4;
    int tda = rem & 15;

    float o4[4][4];
    #pragma unroll
    for (int i = 0; i < 4; i++)
        #pragma unroll
        for (int j = 0; j < 4; j++) o4[i][j] = 0.f;

    for (int kt = 0; kt < ktmax; ++kt) {
        int k0 = kt << 7;
        for (int idx = tid; idx < 128*64; idx += 256) {
            int kk = idx >> 6, d = idx & 63;
            KV[kk*68 + d] = Vg[(size_t)(b*Tc + k0 + kk)*QP + h*HDc + d];
        }
        __syncthreads();
        int kb = ks*64;
        const float* r0 = Sb + (tqa*4+0)*AP + k0 + kb;
        const float* r1 = Sb + (tqa*4+1)*AP + k0 + kb;
        const float* r2 = Sb + (tqa*4+2)*AP + k0 + kb;
        const float* r3 = Sb + (tqa*4+3)*AP + k0 + kb;
        const float* vb = KV + kb*68 + tda*4;
        #pragma unroll 8
        for (int kk = 0; kk < 64; ++kk) {
            float4 vv = *(const float4*)(vb + kk*68);
            float p0 = r0[kk], p1 = r1[kk], p2 = r2[kk], p3 = r3[kk];
            o4[0][0] += p0*vv.x; o4[0][1] += p0*vv.y; o4[0][2] += p0*vv.z; o4[0][3] += p0*vv.w;
            o4[1][0] += p1*vv.x; o4[1][1] += p1*vv.y; o4[1][2] += p1*vv.z; o4[1][3] += p1*vv.w;
            o4[2][0] += p2*vv.x; o4[2][1] += p2*vv.y; o4[2][2] += p2*vv.z; o4[2][3] += p2*vv.w;
            o4[3][0] += p3*vv.x; o4[3][1] += p3*vv.y; o4[3][2] += p3*vv.z; o4[3][3] += p3*vv.w;
        }
        __syncthreads();
    }

    // combine k-halves (Pb reuses Qst area), scale by 1/rowsum, store
    float* Pb = Qst;
    if (ks == 1) {
        #pragma unroll
        for (int i = 0; i < 4; ++i) {
            float4 pv; pv.x = o4[i][0]; pv.y = o4[i][1]; pv.z = o4[i][2]; pv.w = o4[i][3];
            *(float4*)&Pb[(tqa*4+i)*64 + tda*4] = pv;
        }
    }
    __syncthreads();
    if (ks == 0) {
        #pragma unroll
        for (int i = 0; i < 4; ++i) {
            float inv = 1.0f / Ssum[tqa*4 + i];
            float4 pv = *(const float4*)&Pb[(tqa*4+i)*64 + tda*4];
            float4 ov;
            ov.x = (o4[i][0] + pv.x) * inv;
            ov.y = (o4[i][1] + pv.y) * inv;
            ov.z = (o4[i][2] + pv.z) * inv;
            ov.w = (o4[i][3] + pv.w) * inv;
            *(float4*)&Og[(size_t)(b*Tc + q0 + tqa*4 + i)*Dc + h*HDc + tda*4] = ov;
        }
    }
}

// ---------------- residual add + LayerNorm (in-place on x) ------------------
__global__ __launch_bounds__(512)
void add_ln_kernel(float* __restrict__ x, const float* __restrict__ r,
                   const float* __restrict__ g, const float* __restrict__ be)
{
    int tok = blockIdx.x;
    int j = threadIdx.x;
    float v = x[(size_t)tok*Dc + j] + r[(size_t)tok*Dc + j];

    __shared__ float s1[16], s2[16];
    float a = v, b2 = v*v;
    #pragma unroll
    for (int o = 16; o; o >>= 1) {
        a  += __shfl_xor_sync(0xffffffffu, a, o);
        b2 += __shfl_xor_sync(0xffffffffu, b2, o);
    }
    int w = j >> 5, lane = j & 31;
    if (lane == 0) { s1[w] = a; s2[w] = b2; }
    __syncthreads();
    if (j < 16) {
        a = s1[j]; b2 = s2[j];
        #pragma unroll
        for (int o = 8; o; o >>= 1) {
            a  += __shfl_xor_sync(0x0000ffffu, a, o);
            b2 += __shfl_xor_sync(0x0000ffffu, b2, o);
        }
        if (j == 0) { s1[0] = a; s2[0] = b2; }
    }
    __syncthreads();
    float mu  = s1[0] * (1.0f/512.0f);
    float var = s2[0] * (1.0f/512.0f) - mu*mu;
    float y = (v - mu) * rsqrtf(var + 1e-5f) * g[j] + be[j];
    x[(size_t)tok*Dc + j] = y;
}

// ---------------- output head: out[b] = x[b, T-1] @ Wout + bout -------------
__global__ __launch_bounds__(512)
void out_kernel(const float* __restrict__ x, const float* __restrict__ Wout,
                const float* __restrict__ bout, float* __restrict__ out)
{
    int b = blockIdx.x;
    int n = threadIdx.x;
    __shared__ float xs[512];
    xs[n] = x[(size_t)(b*Tc + Tc - 1)*Dc + n];
    __syncthreads();
    float acc = bout[n];
    #pragma unroll 8
    for (int d = 0; d < Dc; ++d)
        acc += xs[d] * Wout[(size_t)d*Dc + n];
    out[b*Dc + n] = acc;
}

// ---------------- launcher ---------------------------------------------------
extern "C" void kernel_launch(void* const* d_in, const int* in_sizes, int n_in,
                              void* d_out, int out_size)
{
    const float* runs    = (const float*)d_in[0];
    const float* wickets = (const float*)d_in[1];
    const float* overs   = (const float*)d_in[2];
    const int*   batters = (const int*)  d_in[3];
    const int*   bowlers = (const int*)  d_in[4];
    const float* pemb    = (const float*)d_in[5];
    const float* Wf      = (const float*)d_in[6];
    const float* bf      = (const float*)d_in[7];
    const float* qtok    = (const float*)d_in[8];
    const float* Wq      = (const float*)d_in[9];
    const float* bq      = (const float*)d_in[10];
    const float* Wk      = (const float*)d_in[11];
    const float* bk      = (const float*)d_in[12];
    const float* Wv      = (const float*)d_in[13];
    const float* bv      = (const float*)d_in[14];
    const float* Wo      = (const float*)d_in[15];
    const float* bo      = (const float*)d_in[16];
    const float* rec_s   = (const float*)d_in[17];
    const float* bow_s   = (const float*)d_in[18];
    const float* bat_s   = (const float*)d_in[19];
    const float* W1      = (const float*)d_in[20];
    const float* b1      = (const float*)d_in[21];
    const float* W2      = (const float*)d_in[22];
    const float* b2      = (const float*)d_in[23];
    const float* g1      = (const float*)d_in[24];
    const float* be1     = (const float*)d_in[25];
    const float* g2      = (const float*)d_in[26];
    const float* be2     = (const float*)d_in[27];
    const float* Wout    = (const float*)d_in[28];
    const float* bout    = (const float*)d_in[29];
    float* out = (float*)d_out;

    float *x_, *att_, *tmp_, *ff_, *wqkv_, *bqkv_;
    cudaGetSymbolAddress((void**)&x_,    g_x);
    cudaGetSymbolAddress((void**)&att_,  g_att);
    cudaGetSymbolAddress((void**)&tmp_,  g_tmp);
    cudaGetSymbolAddress((void**)&ff_,   g_ff);
    cudaGetSymbolAddress((void**)&wqkv_, g_wqkv);
    cudaGetSymbolAddress((void**)&bqkv_, g_bqkv);

    cudaFuncSetAttribute(attn4_kernel,
                         cudaFuncAttributeMaxDynamicSharedMemorySize, ATTN4_SMEM);
    cudaFuncSetAttribute(tgemm_kernel<0>,
                         cudaFuncAttributeMaxDynamicSharedMemorySize, TGEMM_SMEM);
    cudaFuncSetAttribute(tgemm_kernel<1>,
                         cudaFuncAttributeMaxDynamicSharedMemorySize, TGEMM_SMEM);

    pack_qkv_kernel<<<Lc*Dc, 512>>>(Wq, Wk, Wv, wqkv_);
    pack_bqkv_kernel<<<Lc, 512>>>(bq, bk, bv, bqkv_);

    embed_kernel<<<Bc*Tc, 512>>>(runs, wickets, overs, batters, bowlers,
                                 pemb, Wf, bf, qtok, x_);

    dim3 g512 (Dc/TBN,   Mc/TBM);   // (4, 128)
    dim3 gQKV (QP/TBN,   Mc/TBM);   // (12, 128)
    dim3 g2048(DFFc/TBN, Mc/TBM);   // (16, 128)
    dim3 gattn(16, Hc, Bc);

    for (int l = 0; l < Lc; ++l) {
        tgemm_kernel<0><<<gQKV, 256, TGEMM_SMEM>>>(x_, wqkv_ + (size_t)l*Dc*QP,
                                                   bqkv_ + l*QP, ff_, Mc, QP, Dc);

        attn4_kernel<<<gattn, 256, ATTN4_SMEM>>>(ff_, batters, bowlers,
                                                 rec_s, bow_s, bat_s, l, att_);

        tgemm_kernel<0><<<g512, 256, TGEMM_SMEM>>>(att_, Wo + (size_t)l*Dc*Dc,
                                                   bo + l*Dc, tmp_, Mc, Dc, Dc);
        add_ln_kernel<<<Mc, 512>>>(x_, tmp_, g1 + l*Dc, be1 + l*Dc);

        tgemm_kernel<1><<<g2048, 256, TGEMM_SMEM>>>(x_, W1 + (size_t)l*Dc*DFFc,
                                                    b1 + l*DFFc, ff_, Mc, DFFc, Dc);
        tgemm_kernel<0><<<g512, 256, TGEMM_SMEM>>>(ff_, W2 + (size_t)l*DFFc*Dc,
                                                   b2 + l*Dc, tmp_, Mc, Dc, DFFc);
        add_ln_kernel<<<Mc, 512>>>(x_, tmp_, g2 + l*Dc, be2 + l*Dc);
    }

    out_kernel<<<Bc, 512>>>(x_, Wout, bout, out);
}

// round 7
// speedup vs baseline: 1.1952x; 1.0402x over previous
#include <cuda_runtime.h>
#include <cuda_bf16.h>
#include <math_constants.h>
#include <cstdint>

// Problem constants
#define Bc   32
#define Sc   511
#define Tc   512
#define Dc   512
#define Hc   8
#define HDc  64
#define Lc   4
#define PDc  32
#define FDc  448     // D - 2*PD
#define DFFc 2048
#define Mc   (Bc*Tc) // 16384 tokens
#define QP   1536    // qkv combined pitch

// ---------------- scratch (device globals; no allocation allowed) ----------
__device__ float g_x   [Mc*Dc];
__device__ float g_att [Mc*Dc];
__device__ float g_tmp [Mc*Dc];
__device__ float g_ff  [Mc*DFFc];      // doubles as qkv buffer [Mc][1536]
__device__ float g_wqkv[Lc*Dc*QP];
__device__ float g_bqkv[Lc*QP];

// ---------------- weight packing --------------------------------------------
__global__ __launch_bounds__(512)
void pack_qkv_kernel(const float* __restrict__ Wq, const float* __restrict__ Wk,
                     const float* __restrict__ Wv, float* __restrict__ Wqkv)
{
    int lk = blockIdx.x;
    int j  = threadIdx.x;
    size_t src = (size_t)lk*Dc + j;
    size_t dst = (size_t)lk*QP + j;
    Wqkv[dst        ] = Wq[src];
    Wqkv[dst + Dc   ] = Wk[src];
    Wqkv[dst + 2*Dc ] = Wv[src];
}
__global__ __launch_bounds__(512)
void pack_bqkv_kernel(const float* __restrict__ bq, const float* __restrict__ bk,
                      const float* __restrict__ bv, float* __restrict__ bqkv)
{
    int l = blockIdx.x;
    int j = threadIdx.x;
    bqkv[l*QP + j       ] = bq[l*Dc + j];
    bqkv[l*QP + j + Dc  ] = bk[l*Dc + j];
    bqkv[l*QP + j + 2*Dc] = bv[l*Dc + j];
}

// ---------------- embedding + positional encoding ---------------------------
__global__ void embed_kernel(const float* __restrict__ runs,
                             const float* __restrict__ wickets,
                             const float* __restrict__ overs,
                             const int*   __restrict__ batters,
                             const int*   __restrict__ bowlers,
                             const float* __restrict__ pemb,
                             const float* __restrict__ Wf,
                             const float* __restrict__ bf,
                             const float* __restrict__ qtok,
                             float* __restrict__ x)
{
    int bt = blockIdx.x;
    int b  = bt / Tc;
    int t  = bt % Tc;
    int j  = threadIdx.x;

    float val;
    if (t < Sc) {
        if (j < FDc) {
            float r = runs   [b*Sc + t];
            float w = wickets[b*Sc + t];
            float o = overs  [b*Sc + t];
            val = r*Wf[j] + w*Wf[FDc + j] + o*Wf[2*FDc + j] + bf[j];
        } else if (j < FDc + PDc) {
            val = pemb[batters[b*Sc + t]*PDc + (j - FDc)];
        } else {
            val = pemb[bowlers[b*Sc + t]*PDc + (j - FDc - PDc)];
        }
    } else {
        val = qtok[j];
    }
    int   i2  = j & ~1;
    float dv  = expf((float)i2 * -0.0179889460390111f);
    float ang = (float)t * dv;
    val += (j & 1) ? cosf(ang) : sinf(ang);
    x[(b*Tc + t)*Dc + j] = val;
}

// ---------------- helpers -----------------------------------------------------
__device__ __forceinline__ uint32_t smem_u32(const void* p) {
    return (uint32_t)__cvta_generic_to_shared(p);
}
#define MMA_TF32(ACC, A0,A1,A2,A3, B0,B1) \
    asm volatile( \
        "mma.sync.aligned.m16n8k8.row.col.f32.tf32.tf32.f32 " \
        "{%0,%1,%2,%3}, {%4,%5,%6,%7}, {%8,%9}, {%0,%1,%2,%3};\n" \
        : "+f"((ACC)[0]), "+f"((ACC)[1]), "+f"((ACC)[2]), "+f"((ACC)[3]) \
        : "r"(A0), "r"(A1), "r"(A2), "r"(A3), "r"(B0), "r"(B1))
__device__ __forceinline__ uint32_t tf32_hi(float v) {
    uint32_t r; asm("cvt.rna.tf32.f32 %0, %1;" : "=r"(r) : "f"(v)); return r;
}
__device__ __forceinline__ void tf32_split(float v, uint32_t& hi, uint32_t& lo) {
    hi = tf32_hi(v);
    lo = tf32_hi(v - __uint_as_float(hi));
}

// ---------------- tf32 tensor-core GEMM (mma.sync), 2-stage cp.async ---------
#define TBM 128
#define TBN 128
#define TBK 32
#define AST 36
#define BST 136
#define TGEMM_SMEM ((2*TBM*AST + 2*32*BST)*4)

__device__ __forceinline__ void tg_load_stage(
    const float* __restrict__ A, const float* __restrict__ W,
    float* __restrict__ As, float* __restrict__ Bs,
    int bm, int bn, int k0, int K, int N, int tid)
{
    int ar = tid >> 3, aq = tid & 7;
    const float* ap = A + (size_t)(bm*TBM + ar)*K + k0 + aq*4;
    uint32_t ad = smem_u32(As + ar*AST + aq*4);
    #pragma unroll
    for (int i = 0; i < 4; i++) {
        asm volatile("cp.async.cg.shared.global [%0], [%1], 16;\n"
                     :: "r"(ad + i*32*AST*4), "l"(ap + (size_t)i*32*K));
    }
    int br = tid >> 5, bq = tid & 31;
    const float* bp = W + (size_t)(k0 + br)*N + bn*TBN + bq*4;
    uint32_t bd = smem_u32(Bs + br*BST + bq*4);
    #pragma unroll
    for (int i = 0; i < 4; i++) {
        asm volatile("cp.async.cg.shared.global [%0], [%1], 16;\n"
                     :: "r"(bd + i*8*BST*4), "l"(bp + (size_t)i*8*N));
    }
    asm volatile("cp.async.commit_group;\n");
}

template<int EPI>
__global__ __launch_bounds__(256, 2)
void tgemm_kernel(const float* __restrict__ A, const float* __restrict__ W,
                  const float* __restrict__ bias, float* __restrict__ C,
                  int M, int N, int K)
{
    extern __shared__ float sm[];
    float* As = sm;
    float* Bs = sm + 2*TBM*AST;

    int tid = threadIdx.x;
    int bm = blockIdx.y, bn = blockIdx.x;
    int w = tid >> 5, lane = tid & 31;
    int gid = lane >> 2, tig = lane & 3;
    int wm = w >> 2, wn = w & 3;

    float acc[4][4][4];
    #pragma unroll
    for (int i = 0; i < 4; i++)
        #pragma unroll
        for (int j = 0; j < 4; j++)
            #pragma unroll
            for (int r = 0; r < 4; r++) acc[i][j][r] = 0.f;

    int nkt = K / TBK;
    tg_load_stage(A, W, As, Bs, bm, bn, 0, K, N, tid);

    for (int kt = 0; kt < nkt; ++kt) {
        int cur = kt & 1;
        if (kt + 1 < nkt) {
            tg_load_stage(A, W, As + (cur^1)*TBM*AST, Bs + (cur^1)*32*BST,
                          bm, bn, (kt+1)*TBK, K, N, tid);
            asm volatile("cp.async.wait_group 1;\n");
        } else {
            asm volatile("cp.async.wait_group 0;\n");
        }
        __syncthreads();

        const float* Asc = As + cur*TBM*AST;
        const float* Bsc = Bs + cur*32*BST;

        #pragma unroll
        for (int kc = 0; kc < 4; ++kc) {
            uint32_t a[4][4], b[4][2];
            #pragma unroll
            for (int i = 0; i < 4; i++) {
                int r0 = wm*64 + 16*i + gid;
                a[i][0] = __float_as_uint(Asc[(r0    )*AST + kc*8 + tig    ]);
                a[i][1] = __float_as_uint(Asc[(r0 + 8)*AST + kc*8 + tig    ]);
                a[i][2] = __float_as_uint(Asc[(r0    )*AST + kc*8 + tig + 4]);
                a[i][3] = __float_as_uint(Asc[(r0 + 8)*AST + kc*8 + tig + 4]);
            }
            #pragma unroll
            for (int j = 0; j < 4; j++) {
                int c0 = wn*32 + 8*j + gid;
                b[j][0] = __float_as_uint(Bsc[(kc*8 + tig    )*BST + c0]);
                b[j][1] = __float_as_uint(Bsc[(kc*8 + tig + 4)*BST + c0]);
            }
            #pragma unroll
            for (int i = 0; i < 4; i++)
                #pragma unroll
                for (int j = 0; j < 4; j++)
                    MMA_TF32(acc[i][j], a[i][0], a[i][1], a[i][2], a[i][3],
                             b[j][0], b[j][1]);
        }
        __syncthreads();
    }

    #pragma unroll
    for (int i = 0; i < 4; i++) {
        int r = bm*TBM + wm*64 + 16*i + gid;
        #pragma unroll
        for (int j = 0; j < 4; j++) {
            int c = bn*TBN + wn*32 + 8*j + 2*tig;
            float bx = bias[c], by = bias[c+1];
            float v0 = acc[i][j][0] + bx;
            float v1 = acc[i][j][1] + by;
            float v2 = acc[i][j][2] + bx;
            float v3 = acc[i][j][3] + by;
            if (EPI == 1) {
                v0 = 0.5f*v0*(1.0f + erff(v0*0.70710678118654752f));
                v1 = 0.5f*v1*(1.0f + erff(v1*0.70710678118654752f));
                v2 = 0.5f*v2*(1.0f + erff(v2*0.70710678118654752f));
                v3 = 0.5f*v3*(1.0f + erff(v3*0.70710678118654752f));
            }
            float2 p0; p0.x = v0; p0.y = v1;
            float2 p1; p1.x = v2; p1.y = v3;
            *(float2*)&C[(size_t)r*N + c]       = p0;
            *(float2*)&C[(size_t)(r+8)*N + c]   = p1;
        }
    }
}

// ---------------- fused attention v5: 3xtf32 mma -----------------------------
// 32 q rows/block, grid (16,H,B), 256 threads. 64-key chunks.
// Scores and AV via mma.m16n8k8.tf32 with hi/lo split (~fp32 precision).
#define AP 516
// smem (floats): Qhi[32*68]=2176 | Qlo 2176 | KV[64*72]=4608 | Sb[32*516]=16512
//                Mp[32*16]=512 | Ssum 32 | ids 192 ints
#define ATTN5_SMEM ((2176*2 + 4608 + 16512 + 512 + 32 + 192)*4)

__global__ __launch_bounds__(256)
void attn5_kernel(const float* __restrict__ qkv,
                  const int* __restrict__ batters, const int* __restrict__ bowlers,
                  const float* __restrict__ rec_s, const float* __restrict__ bow_s,
                  const float* __restrict__ bat_s, int layer,
                  float* __restrict__ Og)
{
    extern __shared__ float sm[];
    float* Qhi = sm;                  // [32][68]
    float* Qlo = sm + 2176;           // [32][68]
    float* KV  = sm + 4352;           // K: [64][68] natural / V: [64][72] natural
    float* Sb  = sm + 8960;           // [32][516]
    float* Mp  = sm + 25472;          // [32][16]
    float* Ssum= sm + 25984;          // [32]
    int*   ib  = (int*)(sm + 26016);
    int* bowQ = ib;       int* batQ = ib + 32;
    int* bowK = ib + 64;  int* batK = ib + 128;

    int qt = blockIdx.x, h = blockIdx.y, b = blockIdx.z;
    int tid = threadIdx.x;
    int q0 = qt*32;
    int w = tid >> 5, lane = tid & 31;
    int gid = lane >> 2, tig = lane & 3;
    int mi = w >> 2, nq = w & 3;

    const float* Q  = qkv;
    const float* Kg = qkv + Dc;
    const float* Vg = qkv + 2*Dc;

    // Q tile, split into tf32 hi/lo
    for (int idx = tid; idx < 32*64; idx += 256) {
        int q = idx >> 6, d = idx & 63;
        float v = Q[(size_t)(b*Tc + q0 + q)*QP + h*HDc + d];
        uint32_t hv, lv;
        tf32_split(v, hv, lv);
        Qhi[q*68 + d] = __uint_as_float(hv);
        Qlo[q*68 + d] = __uint_as_float(lv);
    }
    if (tid < 32) {
        int qg = q0 + tid;
        bowQ[tid] = (qg < Sc) ? bowlers[b*Sc + qg] : -1;
        batQ[tid] = (qg < Sc) ? batters[b*Sc + qg] : -1;
    }
    __syncthreads();

    int ktmax = (q0 + 32 + 63) >> 6;
    int len   = ktmax << 6;

    const float scl  = 0.125f;
    const float recw = rec_s[layer];
    const float boww = bow_s[layer];
    const float batw = bat_s[layer];

    int r1 = mi*16 + gid, r2 = r1 + 8;
    float mreg[2] = {-CUDART_INF_F, -CUDART_INF_F};

    // ================= scores =================
    for (int kt = 0; kt < ktmax; ++kt) {
        int k0 = kt << 6;
        for (int idx = tid; idx < 64*64; idx += 256) {
            int kk = idx >> 6, d = idx & 63;
            KV[kk*68 + d] = Kg[(size_t)(b*Tc + k0 + kk)*QP + h*HDc + d];
        }
        if (tid < 64) {
            int kg = k0 + tid;
            bowK[tid] = (kg < Sc) ? bowlers[b*Sc + kg] : -2;
            batK[tid] = (kg < Sc) ? batters[b*Sc + kg] : -2;
        }
        __syncthreads();

        float acc[2][4] = {{0,0,0,0},{0,0,0,0}};
        #pragma unroll
        for (int kc = 0; kc < 8; ++kc) {
            int ra = r1*68 + kc*8 + tig;
            uint32_t ah0 = __float_as_uint(Qhi[ra]);
            uint32_t ah1 = __float_as_uint(Qhi[ra + 8*68]);
            uint32_t ah2 = __float_as_uint(Qhi[ra + 4]);
            uint32_t ah3 = __float_as_uint(Qhi[ra + 8*68 + 4]);
            uint32_t al0 = __float_as_uint(Qlo[ra]);
            uint32_t al1 = __float_as_uint(Qlo[ra + 8*68]);
            uint32_t al2 = __float_as_uint(Qlo[ra + 4]);
            uint32_t al3 = __float_as_uint(Qlo[ra + 8*68 + 4]);
            #pragma unroll
            for (int j = 0; j < 2; ++j) {
                int n0 = nq*16 + j*8;
                float b0f = KV[(n0 + gid)*68 + kc*8 + tig];
                float b1f = KV[(n0 + gid)*68 + kc*8 + tig + 4];
                uint32_t bh0, bl0, bh1, bl1;
                tf32_split(b0f, bh0, bl0);
                tf32_split(b1f, bh1, bl1);
                MMA_TF32(acc[j], ah0, ah1, ah2, ah3, bl0, bl1);
                MMA_TF32(acc[j], al0, al1, al2, al3, bh0, bh1);
                MMA_TF32(acc[j], ah0, ah1, ah2, ah3, bh0, bh1);
            }
        }

        // epilogue: scale + bias + causal, track max, store to Sb
        int qg1 = q0 + r1, qg2 = q0 + r2;
        int bq1 = bowQ[r1], aq1 = batQ[r1];
        int bq2 = bowQ[r2], aq2 = batQ[r2];
        #pragma unroll
        for (int j = 0; j < 2; ++j) {
            int kl = nq*16 + j*8 + 2*tig;
            int kg = k0 + kl;
            float s00 = acc[j][0]*scl, s01 = acc[j][1]*scl;
            float s10 = acc[j][2]*scl, s11 = acc[j][3]*scl;
            if (h == 0) {
                s00 += recw * (float)kg     * (1.0f/512.0f);
                s01 += recw * (float)(kg+1) * (1.0f/512.0f);
                s10 += recw * (float)kg     * (1.0f/512.0f);
                s11 += recw * (float)(kg+1) * (1.0f/512.0f);
            } else if (h == 1) {
                int k1b = bowK[kl], k2b = bowK[kl+1];
                if (qg1 == Sc || kg   == Sc || bq1 == k1b) s00 += boww;
                if (qg1 == Sc || kg+1 == Sc || bq1 == k2b) s01 += boww;
                if (qg2 == Sc || kg   == Sc || bq2 == k1b) s10 += boww;
                if (qg2 == Sc || kg+1 == Sc || bq2 == k2b) s11 += boww;
            } else if (h == 2) {
                int k1a = batK[kl], k2a = batK[kl+1];
                if (qg1 == Sc || kg   == Sc || aq1 == k1a) s00 += batw;
                if (qg1 == Sc || kg+1 == Sc || aq1 == k2a) s01 += batw;
                if (qg2 == Sc || kg   == Sc || aq2 == k1a) s10 += batw;
                if (qg2 == Sc || kg+1 == Sc || aq2 == k2a) s11 += batw;
            }
            if (kg   > qg1) s00 = -CUDART_INF_F;
            if (kg+1 > qg1) s01 = -CUDART_INF_F;
            if (kg   > qg2) s10 = -CUDART_INF_F;
            if (kg+1 > qg2) s11 = -CUDART_INF_F;
            mreg[0] = fmaxf(mreg[0], fmaxf(s00, s01));
            mreg[1] = fmaxf(mreg[1], fmaxf(s10, s11));
            float2 p0; p0.x = s00; p0.y = s01;
            float2 p1; p1.x = s10; p1.y = s11;
            *(float2*)&Sb[r1*AP + kg] = p0;
            *(float2*)&Sb[r2*AP + kg] = p1;
        }
        __syncthreads();
    }

    // partial max table
    Mp[r1*16 + nq*4 + tig] = mreg[0];
    Mp[r2*16 + nq*4 + tig] = mreg[1];
    __syncthreads();

    // ================= exp + sum (deferred normalization) =================
    for (int r = w*4; r < w*4 + 4; ++r) {
        float m = Mp[r*16 + (lane & 15)];
        #pragma unroll
        for (int o = 16; o; o >>= 1) m = fmaxf(m, __shfl_xor_sync(0xffffffffu, m, o));
        float* row = Sb + r*AP;
        float ssum = 0.f;
        for (int c = lane; c < len; c += 32) {
            float e = __expf(row[c] - m);
            row[c] = e;
            ssum += e;
        }
        #pragma unroll
        for (int o = 16; o; o >>= 1) ssum += __shfl_xor_sync(0xffffffffu, ssum, o);
        if (lane == 0) Ssum[r] = ssum;
    }
    __syncthreads();

    // ================= AV =================
    float oacc[2][4] = {{0,0,0,0},{0,0,0,0}};
    for (int kt = 0; kt < ktmax; ++kt) {
        int k0 = kt << 6;
        for (int idx = tid; idx < 64*64; idx += 256) {
            int kk = idx >> 6, d = idx & 63;
            KV[kk*72 + d] = Vg[(size_t)(b*Tc + k0 + kk)*QP + h*HDc + d];
        }
        __syncthreads();
        #pragma unroll
        for (int kc = 0; kc < 8; ++kc) {
            float a0f = Sb[r1*AP + k0 + kc*8 + tig];
            float a1f = Sb[r2*AP + k0 + kc*8 + tig];
            float a2f = Sb[r1*AP + k0 + kc*8 + tig + 4];
            float a3f = Sb[r2*AP + k0 + kc*8 + tig + 4];
            uint32_t ah0, al0, ah1, al1, ah2, al2, ah3, al3;
            tf32_split(a0f, ah0, al0);
            tf32_split(a1f, ah1, al1);
            tf32_split(a2f, ah2, al2);
            tf32_split(a3f, ah3, al3);
            #pragma unroll
            for (int j = 0; j < 2; ++j) {
                int n0 = (nq*2 + j)*8;
                float b0f = KV[(kc*8 + tig    )*72 + n0 + gid];
                float b1f = KV[(kc*8 + tig + 4)*72 + n0 + gid];
                uint32_t bh0, bl0, bh1, bl1;
                tf32_split(b0f, bh0, bl0);
                tf32_split(b1f, bh1, bl1);
                MMA_TF32(oacc[j], ah0, ah1, ah2, ah3, bl0, bl1);
                MMA_TF32(oacc[j], al0, al1, al2, al3, bh0, bh1);
                MMA_TF32(oacc[j], ah0, ah1, ah2, ah3, bh0, bh1);
            }
        }
        __syncthreads();
    }

    float inv1 = 1.0f / Ssum[r1];
    float inv2 = 1.0f / Ssum[r2];
    #pragma unroll
    for (int j = 0; j < 2; ++j) {
        int col = (nq*2 + j)*8 + 2*tig;
        float2 o1; o1.x = oacc[j][0]*inv1; o1.y = oacc[j][1]*inv1;
        float2 o2; o2.x = oacc[j][2]*inv2; o2.y = oacc[j][3]*inv2;
        *(float2*)&Og[(size_t)(b*Tc + q0 + r1)*Dc + h*HDc + col] = o1;
        *(float2*)&Og[(size_t)(b*Tc + q0 + r2)*Dc + h*HDc + col] = o2;
    }
}

// ---------------- residual add + LayerNorm (in-place on x) ------------------
__global__ __launch_bounds__(512)
void add_ln_kernel(float* __restrict__ x, const float* __restrict__ r,
                   const float* __restrict__ g, const float* __restrict__ be)
{
    int tok = blockIdx.x;
    int j = threadIdx.x;
    float v = x[(size_t)tok*Dc + j] + r[(size_t)tok*Dc + j];

    __shared__ float s1[16], s2[16];
    float a = v, b2 = v*v;
    #pragma unroll
    for (int o = 16; o; o >>= 1) {
        a  += __shfl_xor_sync(0xffffffffu, a, o);
        b2 += __shfl_xor_sync(0xffffffffu, b2, o);
    }
    int w = j >> 5, lane = j & 31;
    if (lane == 0) { s1[w] = a; s2[w] = b2; }
    __syncthreads();
    if (j < 16) {
        a = s1[j]; b2 = s2[j];
        #pragma unroll
        for (int o = 8; o; o >>= 1) {
            a  += __shfl_xor_sync(0x0000ffffu, a, o);
            b2 += __shfl_xor_sync(0x0000ffffu, b2, o);
        }
        if (j == 0) { s1[0] = a; s2[0] = b2; }
    }
    __syncthreads();
    float mu  = s1[0] * (1.0f/512.0f);
    float var = s2[0] * (1.0f/512.0f) - mu*mu;
    float y = (v - mu) * rsqrtf(var + 1e-5f) * g[j] + be[j];
    x[(size_t)tok*Dc + j] = y;
}

// ---------------- output head: out[b] = x[b, T-1] @ Wout + bout -------------
__global__ __launch_bounds__(512)
void out_kernel(const float* __restrict__ x, const float* __restrict__ Wout,
                const float* __restrict__ bout, float* __restrict__ out)
{
    int b = blockIdx.x;
    int n = threadIdx.x;
    __shared__ float xs[512];
    xs[n] = x[(size_t)(b*Tc + Tc - 1)*Dc + n];
    __syncthreads();
    float acc = bout[n];
    #pragma unroll 8
    for (int d = 0; d < Dc; ++d)
        acc += xs[d] * Wout[(size_t)d*Dc + n];
    out[b*Dc + n] = acc;
}

// ---------------- launcher ---------------------------------------------------
extern "C" void kernel_launch(void* const* d_in, const int* in_sizes, int n_in,
                              void* d_out, int out_size)
{
    const float* runs    = (const float*)d_in[0];
    const float* wickets = (const float*)d_in[1];
    const float* overs   = (const float*)d_in[2];
    const int*   batters = (const int*)  d_in[3];
    const int*   bowlers = (const int*)  d_in[4];
    const float* pemb    = (const float*)d_in[5];
    const float* Wf      = (const float*)d_in[6];
    const float* bf      = (const float*)d_in[7];
    const float* qtok    = (const float*)d_in[8];
    const float* Wq      = (const float*)d_in[9];
    const float* bq      = (const float*)d_in[10];
    const float* Wk      = (const float*)d_in[11];
    const float* bk      = (const float*)d_in[12];
    const float* Wv      = (const float*)d_in[13];
    const float* bv      = (const float*)d_in[14];
    const float* Wo      = (const float*)d_in[15];
    const float* bo      = (const float*)d_in[16];
    const float* rec_s   = (const float*)d_in[17];
    const float* bow_s   = (const float*)d_in[18];
    const float* bat_s   = (const float*)d_in[19];
    const float* W1      = (const float*)d_in[20];
    const float* b1      = (const float*)d_in[21];
    const float* W2      = (const float*)d_in[22];
    const float* b2      = (const float*)d_in[23];
    const float* g1      = (const float*)d_in[24];
    const float* be1     = (const float*)d_in[25];
    const float* g2      = (const float*)d_in[26];
    const float* be2     = (const float*)d_in[27];
    const float* Wout    = (const float*)d_in[28];
    const float* bout    = (const float*)d_in[29];
    float* out = (float*)d_out;

    float *x_, *att_, *tmp_, *ff_, *wqkv_, *bqkv_;
    cudaGetSymbolAddress((void**)&x_,    g_x);
    cudaGetSymbolAddress((void**)&att_,  g_att);
    cudaGetSymbolAddress((void**)&tmp_,  g_tmp);
    cudaGetSymbolAddress((void**)&ff_,   g_ff);
    cudaGetSymbolAddress((void**)&wqkv_, g_wqkv);
    cudaGetSymbolAddress((void**)&bqkv_, g_bqkv);

    cudaFuncSetAttribute(attn5_kernel,
                         cudaFuncAttributeMaxDynamicSharedMemorySize, ATTN5_SMEM);
    cudaFuncSetAttribute(tgemm_kernel<0>,
                         cudaFuncAttributeMaxDynamicSharedMemorySize, TGEMM_SMEM);
    cudaFuncSetAttribute(tgemm_kernel<1>,
                         cudaFuncAttributeMaxDynamicSharedMemorySize, TGEMM_SMEM);

    pack_qkv_kernel<<<Lc*Dc, 512>>>(Wq, Wk, Wv, wqkv_);
    pack_bqkv_kernel<<<Lc, 512>>>(bq, bk, bv, bqkv_);

    embed_kernel<<<Bc*Tc, 512>>>(runs, wickets, overs, batters, bowlers,
                                 pemb, Wf, bf, qtok, x_);

    dim3 g512 (Dc/TBN,   Mc/TBM);   // (4, 128)
    dim3 gQKV (QP/TBN,   Mc/TBM);   // (12, 128)
    dim3 g2048(DFFc/TBN, Mc/TBM);   // (16, 128)
    dim3 gattn(16, Hc, Bc);

    for (int l = 0; l < Lc; ++l) {
        tgemm_kernel<0><<<gQKV, 256, TGEMM_SMEM>>>(x_, wqkv_ + (size_t)l*Dc*QP,
                                                   bqkv_ + l*QP, ff_, Mc, QP, Dc);

        attn5_kernel<<<gattn, 256, ATTN5_SMEM>>>(ff_, batters, bowlers,
                                                 rec_s, bow_s, bat_s, l, att_);

        tgemm_kernel<0><<<g512, 256, TGEMM_SMEM>>>(att_, Wo + (size_t)l*Dc*Dc,
                                                   bo + l*Dc, tmp_, Mc, Dc, Dc);
        add_ln_kernel<<<Mc, 512>>>(x_, tmp_, g1 + l*Dc, be1 + l*Dc);

        tgemm_kernel<1><<<g2048, 256, TGEMM_SMEM>>>(x_, W1 + (size_t)l*Dc*DFFc,
                                                    b1 + l*DFFc, ff_, Mc, DFFc, Dc);
        tgemm_kernel<0><<<g512, 256, TGEMM_SMEM>>>(ff_, W2 + (size_t)l*DFFc*Dc,
                                                   b2 + l*Dc, tmp_, Mc, Dc, DFFc);
        add_ln_kernel<<<Mc, 512>>>(x_, tmp_, g2 + l*Dc, be2 + l*Dc);
    }

    out_kernel<<<Bc, 512>>>(x_, Wout, bout, out);
}

// round 8
// speedup vs baseline: 1.3851x; 1.1589x over previous
#include <cuda_runtime.h>
#include <cuda_bf16.h>
#include <math_constants.h>
#include <cstdint>

// Problem constants
#define Bc   32
#define Sc   511
#define Tc   512
#define Dc   512
#define Hc   8
#define HDc  64
#define Lc   4
#define PDc  32
#define FDc  448     // D - 2*PD
#define DFFc 2048
#define Mc   (Bc*Tc) // 16384 tokens
#define QP   1536    // qkv combined pitch

// ---------------- scratch (device globals; no allocation allowed) ----------
__device__ float g_x   [Mc*Dc];
__device__ float g_att [Mc*Dc];
__device__ float g_tmp [Mc*Dc];
__device__ float g_ff  [Mc*DFFc];      // doubles as qkv buffer [Mc][1536]
__device__ float g_wqkv[Lc*Dc*QP];
__device__ float g_bqkv[Lc*QP];

// ---------------- weight packing --------------------------------------------
__global__ __launch_bounds__(512)
void pack_qkv_kernel(const float* __restrict__ Wq, const float* __restrict__ Wk,
                     const float* __restrict__ Wv, float* __restrict__ Wqkv)
{
    int lk = blockIdx.x;
    int j  = threadIdx.x;
    size_t src = (size_t)lk*Dc + j;
    size_t dst = (size_t)lk*QP + j;
    Wqkv[dst        ] = Wq[src];
    Wqkv[dst + Dc   ] = Wk[src];
    Wqkv[dst + 2*Dc ] = Wv[src];
}
__global__ __launch_bounds__(512)
void pack_bqkv_kernel(const float* __restrict__ bq, const float* __restrict__ bk,
                      const float* __restrict__ bv, float* __restrict__ bqkv)
{
    int l = blockIdx.x;
    int j = threadIdx.x;
    bqkv[l*QP + j       ] = bq[l*Dc + j];
    bqkv[l*QP + j + Dc  ] = bk[l*Dc + j];
    bqkv[l*QP + j + 2*Dc] = bv[l*Dc + j];
}

// ---------------- embedding + positional encoding ---------------------------
__global__ void embed_kernel(const float* __restrict__ runs,
                             const float* __restrict__ wickets,
                             const float* __restrict__ overs,
                             const int*   __restrict__ batters,
                             const int*   __restrict__ bowlers,
                             const float* __restrict__ pemb,
                             const float* __restrict__ Wf,
                             const float* __restrict__ bf,
                             const float* __restrict__ qtok,
                             float* __restrict__ x)
{
    int bt = blockIdx.x;
    int b  = bt / Tc;
    int t  = bt % Tc;
    int j  = threadIdx.x;

    float val;
    if (t < Sc) {
        if (j < FDc) {
            float r = runs   [b*Sc + t];
            float w = wickets[b*Sc + t];
            float o = overs  [b*Sc + t];
            val = r*Wf[j] + w*Wf[FDc + j] + o*Wf[2*FDc + j] + bf[j];
        } else if (j < FDc + PDc) {
            val = pemb[batters[b*Sc + t]*PDc + (j - FDc)];
        } else {
            val = pemb[bowlers[b*Sc + t]*PDc + (j - FDc - PDc)];
        }
    } else {
        val = qtok[j];
    }
    int   i2  = j & ~1;
    float dv  = expf((float)i2 * -0.0179889460390111f);
    float ang = (float)t * dv;
    val += (j & 1) ? cosf(ang) : sinf(ang);
    x[(b*Tc + t)*Dc + j] = val;
}

// ---------------- helpers -----------------------------------------------------
__device__ __forceinline__ uint32_t smem_u32(const void* p) {
    return (uint32_t)__cvta_generic_to_shared(p);
}
#define MMA_TF32(ACC, A0,A1,A2,A3, B0,B1) \
    asm volatile( \
        "mma.sync.aligned.m16n8k8.row.col.f32.tf32.tf32.f32 " \
        "{%0,%1,%2,%3}, {%4,%5,%6,%7}, {%8,%9}, {%0,%1,%2,%3};\n" \
        : "+f"((ACC)[0]), "+f"((ACC)[1]), "+f"((ACC)[2]), "+f"((ACC)[3]) \
        : "r"(A0), "r"(A1), "r"(A2), "r"(A3), "r"(B0), "r"(B1))
__device__ __forceinline__ uint32_t tf32_hi(float v) {
    uint32_t r; asm("cvt.rna.tf32.f32 %0, %1;" : "=r"(r) : "f"(v)); return r;
}
__device__ __forceinline__ void tf32_split(float v, uint32_t& hi, uint32_t& lo) {
    hi = tf32_hi(v);
    lo = tf32_hi(v - __uint_as_float(hi));
}

// ---------------- tf32 tensor-core GEMM (mma.sync), 2-stage cp.async ---------
#define TBM 128
#define TBN 128
#define TBK 32
#define AST 36
#define BST 136
#define TGEMM_SMEM ((2*TBM*AST + 2*32*BST)*4)

__device__ __forceinline__ void tg_load_stage(
    const float* __restrict__ A, const float* __restrict__ W,
    float* __restrict__ As, float* __restrict__ Bs,
    int bm, int bn, int k0, int K, int N, int tid)
{
    int ar = tid >> 3, aq = tid & 7;
    const float* ap = A + (size_t)(bm*TBM + ar)*K + k0 + aq*4;
    uint32_t ad = smem_u32(As + ar*AST + aq*4);
    #pragma unroll
    for (int i = 0; i < 4; i++) {
        asm volatile("cp.async.cg.shared.global [%0], [%1], 16;\n"
                     :: "r"(ad + i*32*AST*4), "l"(ap + (size_t)i*32*K));
    }
    int br = tid >> 5, bq = tid & 31;
    const float* bp = W + (size_t)(k0 + br)*N + bn*TBN + bq*4;
    uint32_t bd = smem_u32(Bs + br*BST + bq*4);
    #pragma unroll
    for (int i = 0; i < 4; i++) {
        asm volatile("cp.async.cg.shared.global [%0], [%1], 16;\n"
                     :: "r"(bd + i*8*BST*4), "l"(bp + (size_t)i*8*N));
    }
    asm volatile("cp.async.commit_group;\n");
}

template<int EPI>
__global__ __launch_bounds__(256, 2)
void tgemm_kernel(const float* __restrict__ A, const float* __restrict__ W,
                  const float* __restrict__ bias, float* __restrict__ C,
                  int M, int N, int K)
{
    extern __shared__ float sm[];
    float* As = sm;
    float* Bs = sm + 2*TBM*AST;

    int tid = threadIdx.x;
    int bm = blockIdx.y, bn = blockIdx.x;
    int w = tid >> 5, lane = tid & 31;
    int gid = lane >> 2, tig = lane & 3;
    int wm = w >> 2, wn = w & 3;

    float acc[4][4][4];
    #pragma unroll
    for (int i = 0; i < 4; i++)
        #pragma unroll
        for (int j = 0; j < 4; j++)
            #pragma unroll
            for (int r = 0; r < 4; r++) acc[i][j][r] = 0.f;

    int nkt = K / TBK;
    tg_load_stage(A, W, As, Bs, bm, bn, 0, K, N, tid);

    for (int kt = 0; kt < nkt; ++kt) {
        int cur = kt & 1;
        if (kt + 1 < nkt) {
            tg_load_stage(A, W, As + (cur^1)*TBM*AST, Bs + (cur^1)*32*BST,
                          bm, bn, (kt+1)*TBK, K, N, tid);
            asm volatile("cp.async.wait_group 1;\n");
        } else {
            asm volatile("cp.async.wait_group 0;\n");
        }
        __syncthreads();

        const float* Asc = As + cur*TBM*AST;
        const float* Bsc = Bs + cur*32*BST;

        #pragma unroll
        for (int kc = 0; kc < 4; ++kc) {
            uint32_t a[4][4], b[4][2];
            #pragma unroll
            for (int i = 0; i < 4; i++) {
                int r0 = wm*64 + 16*i + gid;
                a[i][0] = __float_as_uint(Asc[(r0    )*AST + kc*8 + tig    ]);
                a[i][1] = __float_as_uint(Asc[(r0 + 8)*AST + kc*8 + tig    ]);
                a[i][2] = __float_as_uint(Asc[(r0    )*AST + kc*8 + tig + 4]);
                a[i][3] = __float_as_uint(Asc[(r0 + 8)*AST + kc*8 + tig + 4]);
            }
            #pragma unroll
            for (int j = 0; j < 4; j++) {
                int c0 = wn*32 + 8*j + gid;
                b[j][0] = __float_as_uint(Bsc[(kc*8 + tig    )*BST + c0]);
                b[j][1] = __float_as_uint(Bsc[(kc*8 + tig + 4)*BST + c0]);
            }
            #pragma unroll
            for (int i = 0; i < 4; i++)
                #pragma unroll
                for (int j = 0; j < 4; j++)
                    MMA_TF32(acc[i][j], a[i][0], a[i][1], a[i][2], a[i][3],
                             b[j][0], b[j][1]);
        }
        __syncthreads();
    }

    #pragma unroll
    for (int i = 0; i < 4; i++) {
        int r = bm*TBM + wm*64 + 16*i + gid;
        #pragma unroll
        for (int j = 0; j < 4; j++) {
            int c = bn*TBN + wn*32 + 8*j + 2*tig;
            float bx = bias[c], by = bias[c+1];
            float v0 = acc[i][j][0] + bx;
            float v1 = acc[i][j][1] + by;
            float v2 = acc[i][j][2] + bx;
            float v3 = acc[i][j][3] + by;
            if (EPI == 1) {
                v0 = 0.5f*v0*(1.0f + erff(v0*0.70710678118654752f));
                v1 = 0.5f*v1*(1.0f + erff(v1*0.70710678118654752f));
                v2 = 0.5f*v2*(1.0f + erff(v2*0.70710678118654752f));
                v3 = 0.5f*v3*(1.0f + erff(v3*0.70710678118654752f));
            }
            float2 p0; p0.x = v0; p0.y = v1;
            float2 p1; p1.x = v2; p1.y = v3;
            *(float2*)&C[(size_t)r*N + c]       = p0;
            *(float2*)&C[(size_t)(r+8)*N + c]   = p1;
        }
    }
}

// ---------------- fused attention v6: online softmax + staged hi/lo ----------
// 32 q rows/block, grid (16,H,B), 256 threads, 64-key chunks, single pass.
// All tf32 splits hoisted to staging; inner loops are pure LDS + MMA.
// smem floats:
//   Qhi 0      [32][68]  2176     Qlo 2176   [32][68] 2176
//   Khi 4352   [64][68]  4352     Klo 8704   [64][68] 4352
//   Vhi 13056  [64][72]  4608     Vlo 17664  [64][72] 4608
//   Phi 22272  [32][68]  2176     Plo 24448  [32][68] 2176
//   Mp  26624  [32][4]   128      Sp  26752  [32][4]  128
//   ids 26880  192 ints
#define ATTN6_SMEM (27072*4)

__global__ __launch_bounds__(256)
void attn6_kernel(const float* __restrict__ qkv,
                  const int* __restrict__ batters, const int* __restrict__ bowlers,
                  const float* __restrict__ rec_s, const float* __restrict__ bow_s,
                  const float* __restrict__ bat_s, int layer,
                  float* __restrict__ Og)
{
    extern __shared__ float sm[];
    float* Qhi = sm;
    float* Qlo = sm + 2176;
    float* Khi = sm + 4352;
    float* Klo = sm + 8704;
    float* Vhi = sm + 13056;
    float* Vlo = sm + 17664;
    float* Phi = sm + 22272;
    float* Plo = sm + 24448;
    float* Mp  = sm + 26624;
    float* Sp  = sm + 26752;
    int*   ib  = (int*)(sm + 26880);
    int* bowQ = ib;       int* batQ = ib + 32;
    int* bowK = ib + 64;  int* batK = ib + 128;

    int qt = blockIdx.x, h = blockIdx.y, b = blockIdx.z;
    int tid = threadIdx.x;
    int q0 = qt*32;
    int w = tid >> 5, lane = tid & 31;
    int gid = lane >> 2, tig = lane & 3;
    int mi = w >> 2, nq = w & 3;
    int r1 = mi*16 + gid, r2 = r1 + 8;

    const float* Q  = qkv;
    const float* Kg = qkv + Dc;
    const float* Vg = qkv + 2*Dc;

    // stage Q split hi/lo (float4 granularity)
    #pragma unroll
    for (int it = 0; it < 2; ++it) {
        int idx = tid + it*256;        // 0..511, covers 32x16 float4s
        int q = idx >> 4, d4 = idx & 15;
        float4 v = *(const float4*)&Q[(size_t)(b*Tc + q0 + q)*QP + h*HDc + d4*4];
        uint32_t h0,l0,h1,l1,h2,l2,h3,l3;
        tf32_split(v.x, h0, l0); tf32_split(v.y, h1, l1);
        tf32_split(v.z, h2, l2); tf32_split(v.w, h3, l3);
        float4 hv, lv;
        hv.x = __uint_as_float(h0); hv.y = __uint_as_float(h1);
        hv.z = __uint_as_float(h2); hv.w = __uint_as_float(h3);
        lv.x = __uint_as_float(l0); lv.y = __uint_as_float(l1);
        lv.z = __uint_as_float(l2); lv.w = __uint_as_float(l3);
        *(float4*)&Qhi[q*68 + d4*4] = hv;
        *(float4*)&Qlo[q*68 + d4*4] = lv;
    }
    if (tid < 32) {
        int qg = q0 + tid;
        bowQ[tid] = (qg < Sc) ? bowlers[b*Sc + qg] : -1;
        batQ[tid] = (qg < Sc) ? batters[b*Sc + qg] : -1;
    }

    int ktmax = (q0 + 32 + 63) >> 6;
    const float scl  = 0.125f;
    const float recw = rec_s[layer];
    const float boww = bow_s[layer];
    const float batw = bat_s[layer];

    int qg1 = q0 + r1, qg2 = q0 + r2;

    float oacc[2][4] = {{0,0,0,0},{0,0,0,0}};
    float mrun1 = -1e30f, mrun2 = -1e30f;
    float srun1 = 0.f,    srun2 = 0.f;

    for (int kt = 0; kt < ktmax; ++kt) {
        int k0 = kt << 6;

        // ---- stage K split hi/lo ----
        #pragma unroll
        for (int it = 0; it < 4; ++it) {
            int idx = tid + it*256;    // 0..1023, 64x16 float4s
            int kk = idx >> 4, d4 = idx & 15;
            float4 v = *(const float4*)&Kg[(size_t)(b*Tc + k0 + kk)*QP + h*HDc + d4*4];
            uint32_t h0,l0,h1,l1,h2,l2,h3,l3;
            tf32_split(v.x, h0, l0); tf32_split(v.y, h1, l1);
            tf32_split(v.z, h2, l2); tf32_split(v.w, h3, l3);
            float4 hv, lv;
            hv.x = __uint_as_float(h0); hv.y = __uint_as_float(h1);
            hv.z = __uint_as_float(h2); hv.w = __uint_as_float(h3);
            lv.x = __uint_as_float(l0); lv.y = __uint_as_float(l1);
            lv.z = __uint_as_float(l2); lv.w = __uint_as_float(l3);
            *(float4*)&Khi[kk*68 + d4*4] = hv;
            *(float4*)&Klo[kk*68 + d4*4] = lv;
        }
        if (tid < 64) {
            int kg = k0 + tid;
            bowK[tid] = (kg < Sc) ? bowlers[b*Sc + kg] : -2;
            batK[tid] = (kg < Sc) ? batters[b*Sc + kg] : -2;
        }
        __syncthreads();   // S1: K/ids staged (also: all warps done with prev AV)

        // ---- score MMA ----
        float acc[2][4] = {{0,0,0,0},{0,0,0,0}};
        #pragma unroll
        for (int kc = 0; kc < 8; ++kc) {
            int ra = r1*68 + kc*8 + tig;
            uint32_t ah0 = __float_as_uint(Qhi[ra]);
            uint32_t ah1 = __float_as_uint(Qhi[ra + 8*68]);
            uint32_t ah2 = __float_as_uint(Qhi[ra + 4]);
            uint32_t ah3 = __float_as_uint(Qhi[ra + 8*68 + 4]);
            uint32_t al0 = __float_as_uint(Qlo[ra]);
            uint32_t al1 = __float_as_uint(Qlo[ra + 8*68]);
            uint32_t al2 = __float_as_uint(Qlo[ra + 4]);
            uint32_t al3 = __float_as_uint(Qlo[ra + 8*68 + 4]);
            #pragma unroll
            for (int j = 0; j < 2; ++j) {
                int rb = (nq*16 + j*8 + gid)*68 + kc*8 + tig;
                uint32_t bh0 = __float_as_uint(Khi[rb]);
                uint32_t bh1 = __float_as_uint(Khi[rb + 4]);
                uint32_t bl0 = __float_as_uint(Klo[rb]);
                uint32_t bl1 = __float_as_uint(Klo[rb + 4]);
                MMA_TF32(acc[j], ah0, ah1, ah2, ah3, bl0, bl1);
                MMA_TF32(acc[j], al0, al1, al2, al3, bh0, bh1);
                MMA_TF32(acc[j], ah0, ah1, ah2, ah3, bh0, bh1);
            }
        }

        // ---- stage V split hi/lo (V buffers free: prev AV done before S1) ----
        #pragma unroll
        for (int it = 0; it < 4; ++it) {
            int idx = tid + it*256;
            int kk = idx >> 4, d4 = idx & 15;
            float4 v = *(const float4*)&Vg[(size_t)(b*Tc + k0 + kk)*QP + h*HDc + d4*4];
            uint32_t h0,l0,h1,l1,h2,l2,h3,l3;
            tf32_split(v.x, h0, l0); tf32_split(v.y, h1, l1);
            tf32_split(v.z, h2, l2); tf32_split(v.w, h3, l3);
            float4 hv, lv;
            hv.x = __uint_as_float(h0); hv.y = __uint_as_float(h1);
            hv.z = __uint_as_float(h2); hv.w = __uint_as_float(h3);
            lv.x = __uint_as_float(l0); lv.y = __uint_as_float(l1);
            lv.z = __uint_as_float(l2); lv.w = __uint_as_float(l3);
            *(float4*)&Vhi[kk*72 + d4*4] = hv;
            *(float4*)&Vlo[kk*72 + d4*4] = lv;
        }

        // ---- score epilogue: scale + bias + causal ----
        float sv[2][4];
        int bq1 = bowQ[r1], aq1 = batQ[r1];
        int bq2 = bowQ[r2], aq2 = batQ[r2];
        #pragma unroll
        for (int j = 0; j < 2; ++j) {
            int kl = nq*16 + j*8 + 2*tig;
            int kg = k0 + kl;
            float s00 = acc[j][0]*scl, s01 = acc[j][1]*scl;
            float s10 = acc[j][2]*scl, s11 = acc[j][3]*scl;
            if (h == 0) {
                s00 += recw * (float)kg     * (1.0f/512.0f);
                s01 += recw * (float)(kg+1) * (1.0f/512.0f);
                s10 += recw * (float)kg     * (1.0f/512.0f);
                s11 += recw * (float)(kg+1) * (1.0f/512.0f);
            } else if (h == 1) {
                int k1b = bowK[kl], k2b = bowK[kl+1];
                if (qg1 == Sc || kg   == Sc || bq1 == k1b) s00 += boww;
                if (qg1 == Sc || kg+1 == Sc || bq1 == k2b) s01 += boww;
                if (qg2 == Sc || kg   == Sc || bq2 == k1b) s10 += boww;
                if (qg2 == Sc || kg+1 == Sc || bq2 == k2b) s11 += boww;
            } else if (h == 2) {
                int k1a = batK[kl], k2a = batK[kl+1];
                if (qg1 == Sc || kg   == Sc || aq1 == k1a) s00 += batw;
                if (qg1 == Sc || kg+1 == Sc || aq1 == k2a) s01 += batw;
                if (qg2 == Sc || kg   == Sc || aq2 == k1a) s10 += batw;
                if (qg2 == Sc || kg+1 == Sc || aq2 == k2a) s11 += batw;
            }
            if (kg   > qg1) s00 = -1e30f;
            if (kg+1 > qg1) s01 = -1e30f;
            if (kg   > qg2) s10 = -1e30f;
            if (kg+1 > qg2) s11 = -1e30f;
            sv[j][0] = s00; sv[j][1] = s01; sv[j][2] = s10; sv[j][3] = s11;
        }

        // ---- chunk row-max: quad shfl + cross-warp smem ----
        float rm1 = fmaxf(fmaxf(sv[0][0], sv[0][1]), fmaxf(sv[1][0], sv[1][1]));
        float rm2 = fmaxf(fmaxf(sv[0][2], sv[0][3]), fmaxf(sv[1][2], sv[1][3]));
        rm1 = fmaxf(rm1, __shfl_xor_sync(0xffffffffu, rm1, 1));
        rm1 = fmaxf(rm1, __shfl_xor_sync(0xffffffffu, rm1, 2));
        rm2 = fmaxf(rm2, __shfl_xor_sync(0xffffffffu, rm2, 1));
        rm2 = fmaxf(rm2, __shfl_xor_sync(0xffffffffu, rm2, 2));
        if (tig == 0) { Mp[r1*4 + nq] = rm1; Mp[r2*4 + nq] = rm2; }
        __syncthreads();   // S2a: Mp visible + V staging complete

        float4 m4a = *(const float4*)&Mp[r1*4];
        float4 m4b = *(const float4*)&Mp[r2*4];
        float mc1 = fmaxf(fmaxf(m4a.x, m4a.y), fmaxf(m4a.z, m4a.w));
        float mc2 = fmaxf(fmaxf(m4b.x, m4b.y), fmaxf(m4b.z, m4b.w));
        float mnew1 = fmaxf(mrun1, mc1);
        float mnew2 = fmaxf(mrun2, mc2);
        float f1 = __expf(mrun1 - mnew1);
        float f2 = __expf(mrun2 - mnew2);

        // ---- exp, write P split hi/lo, partial sums ----
        float ps1 = 0.f, ps2 = 0.f;
        #pragma unroll
        for (int j = 0; j < 2; ++j) {
            int col = nq*16 + j*8 + 2*tig;
            float e00 = __expf(sv[j][0] - mnew1);
            float e01 = __expf(sv[j][1] - mnew1);
            float e10 = __expf(sv[j][2] - mnew2);
            float e11 = __expf(sv[j][3] - mnew2);
            ps1 += e00 + e01;
            ps2 += e10 + e11;
            uint32_t h0,l0,h1,l1;
            tf32_split(e00, h0, l0); tf32_split(e01, h1, l1);
            float2 hv, lv;
            hv.x = __uint_as_float(h0); hv.y = __uint_as_float(h1);
            lv.x = __uint_as_float(l0); lv.y = __uint_as_float(l1);
            *(float2*)&Phi[r1*68 + col] = hv;
            *(float2*)&Plo[r1*68 + col] = lv;
            tf32_split(e10, h0, l0); tf32_split(e11, h1, l1);
            hv.x = __uint_as_float(h0); hv.y = __uint_as_float(h1);
            lv.x = __uint_as_float(l0); lv.y = __uint_as_float(l1);
            *(float2*)&Phi[r2*68 + col] = hv;
            *(float2*)&Plo[r2*68 + col] = lv;
        }
        ps1 += __shfl_xor_sync(0xffffffffu, ps1, 1);
        ps1 += __shfl_xor_sync(0xffffffffu, ps1, 2);
        ps2 += __shfl_xor_sync(0xffffffffu, ps2, 1);
        ps2 += __shfl_xor_sync(0xffffffffu, ps2, 2);
        if (tig == 0) { Sp[r1*4 + nq] = ps1; Sp[r2*4 + nq] = ps2; }

        // ---- rescale running accumulators ----
        oacc[0][0] *= f1; oacc[0][1] *= f1; oacc[1][0] *= f1; oacc[1][1] *= f1;
        oacc[0][2] *= f2; oacc[0][3] *= f2; oacc[1][2] *= f2; oacc[1][3] *= f2;
        mrun1 = mnew1; mrun2 = mnew2;
        __syncthreads();   // S2b: P + Sp visible

        float4 s4a = *(const float4*)&Sp[r1*4];
        float4 s4b = *(const float4*)&Sp[r2*4];
        srun1 = srun1*f1 + (s4a.x + s4a.y + s4a.z + s4a.w);
        srun2 = srun2*f2 + (s4b.x + s4b.y + s4b.z + s4b.w);

        // ---- AV MMA (unnormalized) ----
        #pragma unroll
        for (int kc = 0; kc < 8; ++kc) {
            int pa1 = r1*68 + kc*8 + tig;
            int pa2 = r2*68 + kc*8 + tig;
            uint32_t ah0 = __float_as_uint(Phi[pa1]);
            uint32_t ah1 = __float_as_uint(Phi[pa2]);
            uint32_t ah2 = __float_as_uint(Phi[pa1 + 4]);
            uint32_t ah3 = __float_as_uint(Phi[pa2 + 4]);
            uint32_t al0 = __float_as_uint(Plo[pa1]);
            uint32_t al1 = __float_as_uint(Plo[pa2]);
            uint32_t al2 = __float_as_uint(Plo[pa1 + 4]);
            uint32_t al3 = __float_as_uint(Plo[pa2 + 4]);
            #pragma unroll
            for (int j = 0; j < 2; ++j) {
                int n0 = (nq*2 + j)*8;
                int vb0 = (kc*8 + tig    )*72 + n0 + gid;
                int vb1 = (kc*8 + tig + 4)*72 + n0 + gid;
                uint32_t bh0 = __float_as_uint(Vhi[vb0]);
                uint32_t bh1 = __float_as_uint(Vhi[vb1]);
                uint32_t bl0 = __float_as_uint(Vlo[vb0]);
                uint32_t bl1 = __float_as_uint(Vlo[vb1]);
                MMA_TF32(oacc[j], ah0, ah1, ah2, ah3, bl0, bl1);
                MMA_TF32(oacc[j], al0, al1, al2, al3, bh0, bh1);
                MMA_TF32(oacc[j], ah0, ah1, ah2, ah3, bh0, bh1);
            }
        }
    }

    float inv1 = 1.0f / srun1;
    float inv2 = 1.0f / srun2;
    #pragma unroll
    for (int j = 0; j < 2; ++j) {
        int col = (nq*2 + j)*8 + 2*tig;
        float2 o1; o1.x = oacc[j][0]*inv1; o1.y = oacc[j][1]*inv1;
        float2 o2; o2.x = oacc[j][2]*inv2; o2.y = oacc[j][3]*inv2;
        *(float2*)&Og[(size_t)(b*Tc + q0 + r1)*Dc + h*HDc + col] = o1;
        *(float2*)&Og[(size_t)(b*Tc + q0 + r2)*Dc + h*HDc + col] = o2;
    }
}

// ---------------- residual add + LayerNorm (in-place on x) ------------------
__global__ __launch_bounds__(512)
void add_ln_kernel(float* __restrict__ x, const float* __restrict__ r,
                   const float* __restrict__ g, const float* __restrict__ be)
{
    int tok = blockIdx.x;
    int j = threadIdx.x;
    float v = x[(size_t)tok*Dc + j] + r[(size_t)tok*Dc + j];

    __shared__ float s1[16], s2[16];
    float a = v, b2 = v*v;
    #pragma unroll
    for (int o = 16; o; o >>= 1) {
        a  += __shfl_xor_sync(0xffffffffu, a, o);
        b2 += __shfl_xor_sync(0xffffffffu, b2, o);
    }
    int w = j >> 5, lane = j & 31;
    if (lane == 0) { s1[w] = a; s2[w] = b2; }
    __syncthreads();
    if (j < 16) {
        a = s1[j]; b2 = s2[j];
        #pragma unroll
        for (int o = 8; o; o >>= 1) {
            a  += __shfl_xor_sync(0x0000ffffu, a, o);
            b2 += __shfl_xor_sync(0x0000ffffu, b2, o);
        }
        if (j == 0) { s1[0] = a; s2[0] = b2; }
    }
    __syncthreads();
    float mu  = s1[0] * (1.0f/512.0f);
    float var = s2[0] * (1.0f/512.0f) - mu*mu;
    float y = (v - mu) * rsqrtf(var + 1e-5f) * g[j] + be[j];
    x[(size_t)tok*Dc + j] = y;
}

// ---------------- output head: out[b] = x[b, T-1] @ Wout + bout -------------
__global__ __launch_bounds__(512)
void out_kernel(const float* __restrict__ x, const float* __restrict__ Wout,
                const float* __restrict__ bout, float* __restrict__ out)
{
    int b = blockIdx.x;
    int n = threadIdx.x;
    __shared__ float xs[512];
    xs[n] = x[(size_t)(b*Tc + Tc - 1)*Dc + n];
    __syncthreads();
    float acc = bout[n];
    #pragma unroll 8
    for (int d = 0; d < Dc; ++d)
        acc += xs[d] * Wout[(size_t)d*Dc + n];
    out[b*Dc + n] = acc;
}

// ---------------- launcher ---------------------------------------------------
extern "C" void kernel_launch(void* const* d_in, const int* in_sizes, int n_in,
                              void* d_out, int out_size)
{
    const float* runs    = (const float*)d_in[0];
    const float* wickets = (const float*)d_in[1];
    const float* overs   = (const float*)d_in[2];
    const int*   batters = (const int*)  d_in[3];
    const int*   bowlers = (const int*)  d_in[4];
    const float* pemb    = (const float*)d_in[5];
    const float* Wf      = (const float*)d_in[6];
    const float* bf      = (const float*)d_in[7];
    const float* qtok    = (const float*)d_in[8];
    const float* Wq      = (const float*)d_in[9];
    const float* bq      = (const float*)d_in[10];
    const float* Wk      = (const float*)d_in[11];
    const float* bk      = (const float*)d_in[12];
    const float* Wv      = (const float*)d_in[13];
    const float* bv      = (const float*)d_in[14];
    const float* Wo      = (const float*)d_in[15];
    const float* bo      = (const float*)d_in[16];
    const float* rec_s   = (const float*)d_in[17];
    const float* bow_s   = (const float*)d_in[18];
    const float* bat_s   = (const float*)d_in[19];
    const float* W1      = (const float*)d_in[20];
    const float* b1      = (const float*)d_in[21];
    const float* W2      = (const float*)d_in[22];
    const float* b2      = (const float*)d_in[23];
    const float* g1      = (const float*)d_in[24];
    const float* be1     = (const float*)d_in[25];
    const float* g2      = (const float*)d_in[26];
    const float* be2     = (const float*)d_in[27];
    const float* Wout    = (const float*)d_in[28];
    const float* bout    = (const float*)d_in[29];
    float* out = (float*)d_out;

    float *x_, *att_, *tmp_, *ff_, *wqkv_, *bqkv_;
    cudaGetSymbolAddress((void**)&x_,    g_x);
    cudaGetSymbolAddress((void**)&att_,  g_att);
    cudaGetSymbolAddress((void**)&tmp_,  g_tmp);
    cudaGetSymbolAddress((void**)&ff_,   g_ff);
    cudaGetSymbolAddress((void**)&wqkv_, g_wqkv);
    cudaGetSymbolAddress((void**)&bqkv_, g_bqkv);

    cudaFuncSetAttribute(attn6_kernel,
                         cudaFuncAttributeMaxDynamicSharedMemorySize, ATTN6_SMEM);
    cudaFuncSetAttribute(tgemm_kernel<0>,
                         cudaFuncAttributeMaxDynamicSharedMemorySize, TGEMM_SMEM);
    cudaFuncSetAttribute(tgemm_kernel<1>,
                         cudaFuncAttributeMaxDynamicSharedMemorySize, TGEMM_SMEM);

    pack_qkv_kernel<<<Lc*Dc, 512>>>(Wq, Wk, Wv, wqkv_);
    pack_bqkv_kernel<<<Lc, 512>>>(bq, bk, bv, bqkv_);

    embed_kernel<<<Bc*Tc, 512>>>(runs, wickets, overs, batters, bowlers,
                                 pemb, Wf, bf, qtok, x_);

    dim3 g512 (Dc/TBN,   Mc/TBM);   // (4, 128)
    dim3 gQKV (QP/TBN,   Mc/TBM);   // (12, 128)
    dim3 g2048(DFFc/TBN, Mc/TBM);   // (16, 128)
    dim3 gattn(16, Hc, Bc);

    for (int l = 0; l < Lc; ++l) {
        tgemm_kernel<0><<<gQKV, 256, TGEMM_SMEM>>>(x_, wqkv_ + (size_t)l*Dc*QP,
                                                   bqkv_ + l*QP, ff_, Mc, QP, Dc);

        attn6_kernel<<<gattn, 256, ATTN6_SMEM>>>(ff_, batters, bowlers,
                                                 rec_s, bow_s, bat_s, l, att_);

        tgemm_kernel<0><<<g512, 256, TGEMM_SMEM>>>(att_, Wo + (size_t)l*Dc*Dc,
                                                   bo + l*Dc, tmp_, Mc, Dc, Dc);
        add_ln_kernel<<<Mc, 512>>>(x_, tmp_, g1 + l*Dc, be1 + l*Dc);

        tgemm_kernel<1><<<g2048, 256, TGEMM_SMEM>>>(x_, W1 + (size_t)l*Dc*DFFc,
                                                    b1 + l*DFFc, ff_, Mc, DFFc, Dc);
        tgemm_kernel<0><<<g512, 256, TGEMM_SMEM>>>(ff_, W2 + (size_t)l*DFFc*Dc,
                                                   b2 + l*Dc, tmp_, Mc, Dc, DFFc);
        add_ln_kernel<<<Mc, 512>>>(x_, tmp_, g2 + l*Dc, be2 + l*Dc);
    }

    out_kernel<<<Bc, 512>>>(x_, Wout, bout, out);
}

// round 9
// speedup vs baseline: 1.4250x; 1.0288x over previous
#include <cuda_runtime.h>
#include <cuda_bf16.h>
#include <math_constants.h>
#include <cstdint>

// Problem constants
#define Bc   32
#define Sc   511
#define Tc   512
#define Dc   512
#define Hc   8
#define HDc  64
#define Lc   4
#define PDc  32
#define FDc  448     // D - 2*PD
#define DFFc 2048
#define Mc   (Bc*Tc) // 16384 tokens
#define QP   1536    // qkv combined pitch

// ---------------- scratch (device globals; no allocation allowed) ----------
__device__ float g_x   [Mc*Dc];
__device__ float g_att [Mc*Dc];
__device__ float g_tmp [Mc*Dc];
__device__ float g_ff  [Mc*DFFc];      // doubles as qkv buffer [Mc][1536]
__device__ float g_wqkv[Lc*Dc*QP];
__device__ float g_bqkv[Lc*QP];

// ---------------- weight packing --------------------------------------------
__global__ __launch_bounds__(512)
void pack_qkv_kernel(const float* __restrict__ Wq, const float* __restrict__ Wk,
                     const float* __restrict__ Wv, float* __restrict__ Wqkv)
{
    int lk = blockIdx.x;
    int j  = threadIdx.x;
    size_t src = (size_t)lk*Dc + j;
    size_t dst = (size_t)lk*QP + j;
    Wqkv[dst        ] = Wq[src];
    Wqkv[dst + Dc   ] = Wk[src];
    Wqkv[dst + 2*Dc ] = Wv[src];
}
__global__ __launch_bounds__(512)
void pack_bqkv_kernel(const float* __restrict__ bq, const float* __restrict__ bk,
                      const float* __restrict__ bv, float* __restrict__ bqkv)
{
    int l = blockIdx.x;
    int j = threadIdx.x;
    bqkv[l*QP + j       ] = bq[l*Dc + j];
    bqkv[l*QP + j + Dc  ] = bk[l*Dc + j];
    bqkv[l*QP + j + 2*Dc] = bv[l*Dc + j];
}

// ---------------- embedding + positional encoding ---------------------------
__global__ void embed_kernel(const float* __restrict__ runs,
                             const float* __restrict__ wickets,
                             const float* __restrict__ overs,
                             const int*   __restrict__ batters,
                             const int*   __restrict__ bowlers,
                             const float* __restrict__ pemb,
                             const float* __restrict__ Wf,
                             const float* __restrict__ bf,
                             const float* __restrict__ qtok,
                             float* __restrict__ x)
{
    int bt = blockIdx.x;
    int b  = bt / Tc;
    int t  = bt % Tc;
    int j  = threadIdx.x;

    float val;
    if (t < Sc) {
        if (j < FDc) {
            float r = runs   [b*Sc + t];
            float w = wickets[b*Sc + t];
            float o = overs  [b*Sc + t];
            val = r*Wf[j] + w*Wf[FDc + j] + o*Wf[2*FDc + j] + bf[j];
        } else if (j < FDc + PDc) {
            val = pemb[batters[b*Sc + t]*PDc + (j - FDc)];
        } else {
            val = pemb[bowlers[b*Sc + t]*PDc + (j - FDc - PDc)];
        }
    } else {
        val = qtok[j];
    }
    int   i2  = j & ~1;
    float dv  = expf((float)i2 * -0.0179889460390111f);
    float ang = (float)t * dv;
    val += (j & 1) ? cosf(ang) : sinf(ang);
    x[(b*Tc + t)*Dc + j] = val;
}

// ---------------- helpers -----------------------------------------------------
__device__ __forceinline__ uint32_t smem_u32(const void* p) {
    return (uint32_t)__cvta_generic_to_shared(p);
}
#define MMA_TF32(ACC, A0,A1,A2,A3, B0,B1) \
    asm volatile( \
        "mma.sync.aligned.m16n8k8.row.col.f32.tf32.tf32.f32 " \
        "{%0,%1,%2,%3}, {%4,%5,%6,%7}, {%8,%9}, {%0,%1,%2,%3};\n" \
        : "+f"((ACC)[0]), "+f"((ACC)[1]), "+f"((ACC)[2]), "+f"((ACC)[3]) \
        : "r"(A0), "r"(A1), "r"(A2), "r"(A3), "r"(B0), "r"(B1))
__device__ __forceinline__ uint32_t tf32_hi(float v) {
    uint32_t r; asm("cvt.rna.tf32.f32 %0, %1;" : "=r"(r) : "f"(v)); return r;
}
__device__ __forceinline__ void tf32_split(float v, uint32_t& hi, uint32_t& lo) {
    hi = tf32_hi(v);
    lo = tf32_hi(v - __uint_as_float(hi));
}

// ---------------- tf32 tensor-core GEMM, 3-stage cp.async, 1 sync/chunk ------
#define TBM 128
#define TBN 128
#define TBK 32
#define AST 36
#define BST 136
#define TG_ST 3
#define TGEMM_SMEM ((TG_ST*TBM*AST + TG_ST*32*BST)*4)

__device__ __forceinline__ void tg_load_stage(
    const float* __restrict__ A, const float* __restrict__ W,
    float* __restrict__ As, float* __restrict__ Bs,
    int bm, int bn, int k0, int K, int N, int tid)
{
    int ar = tid >> 3, aq = tid & 7;
    const float* ap = A + (size_t)(bm*TBM + ar)*K + k0 + aq*4;
    uint32_t ad = smem_u32(As + ar*AST + aq*4);
    #pragma unroll
    for (int i = 0; i < 4; i++) {
        asm volatile("cp.async.cg.shared.global [%0], [%1], 16;\n"
                     :: "r"(ad + i*32*AST*4), "l"(ap + (size_t)i*32*K));
    }
    int br = tid >> 5, bq = tid & 31;
    const float* bp = W + (size_t)(k0 + br)*N + bn*TBN + bq*4;
    uint32_t bd = smem_u32(Bs + br*BST + bq*4);
    #pragma unroll
    for (int i = 0; i < 4; i++) {
        asm volatile("cp.async.cg.shared.global [%0], [%1], 16;\n"
                     :: "r"(bd + i*8*BST*4), "l"(bp + (size_t)i*8*N));
    }
    asm volatile("cp.async.commit_group;\n");
}

template<int EPI>
__global__ __launch_bounds__(256, 2)
void tgemm_kernel(const float* __restrict__ A, const float* __restrict__ W,
                  const float* __restrict__ bias, float* __restrict__ C,
                  int M, int N, int K)
{
    extern __shared__ float sm[];
    float* As = sm;                         // [3][128*AST]
    float* Bs = sm + TG_ST*TBM*AST;         // [3][32*BST]

    int tid = threadIdx.x;
    int bm = blockIdx.y, bn = blockIdx.x;
    int w = tid >> 5, lane = tid & 31;
    int gid = lane >> 2, tig = lane & 3;
    int wm = w >> 2, wn = w & 3;

    float acc[4][4][4];
    #pragma unroll
    for (int i = 0; i < 4; i++)
        #pragma unroll
        for (int j = 0; j < 4; j++)
            #pragma unroll
            for (int r = 0; r < 4; r++) acc[i][j][r] = 0.f;

    int nkt = K / TBK;
    // prologue: stages for k-chunks 0 and 1
    tg_load_stage(A, W, As, Bs, bm, bn, 0, K, N, tid);
    if (nkt > 1)
        tg_load_stage(A, W, As + TBM*AST, Bs + 32*BST, bm, bn, TBK, K, N, tid);

    for (int kt = 0; kt < nkt; ++kt) {
        // ensure stage kt resident (this thread), leave kt+1 in flight
        if (kt + 1 < nkt) asm volatile("cp.async.wait_group 1;\n");
        else              asm volatile("cp.async.wait_group 0;\n");
        // single barrier: (a) stage kt visible from all threads,
        // (b) all warps done computing kt-1 -> its buffer (== kt+2's) is free
        __syncthreads();
        if (kt + 2 < nkt) {
            int nxt = (kt + 2) % TG_ST;
            tg_load_stage(A, W, As + nxt*TBM*AST, Bs + nxt*32*BST,
                          bm, bn, (kt+2)*TBK, K, N, tid);
        }

        const float* Asc = As + (kt % TG_ST)*TBM*AST;
        const float* Bsc = Bs + (kt % TG_ST)*32*BST;

        #pragma unroll
        for (int kc = 0; kc < 4; ++kc) {
            uint32_t a[4][4], b[4][2];
            #pragma unroll
            for (int i = 0; i < 4; i++) {
                int r0 = wm*64 + 16*i + gid;
                a[i][0] = __float_as_uint(Asc[(r0    )*AST + kc*8 + tig    ]);
                a[i][1] = __float_as_uint(Asc[(r0 + 8)*AST + kc*8 + tig    ]);
                a[i][2] = __float_as_uint(Asc[(r0    )*AST + kc*8 + tig + 4]);
                a[i][3] = __float_as_uint(Asc[(r0 + 8)*AST + kc*8 + tig + 4]);
            }
            #pragma unroll
            for (int j = 0; j < 4; j++) {
                int c0 = wn*32 + 8*j + gid;
                b[j][0] = __float_as_uint(Bsc[(kc*8 + tig    )*BST + c0]);
                b[j][1] = __float_as_uint(Bsc[(kc*8 + tig + 4)*BST + c0]);
            }
            #pragma unroll
            for (int i = 0; i < 4; i++)
                #pragma unroll
                for (int j = 0; j < 4; j++)
                    MMA_TF32(acc[i][j], a[i][0], a[i][1], a[i][2], a[i][3],
                             b[j][0], b[j][1]);
        }
    }

    #pragma unroll
    for (int i = 0; i < 4; i++) {
        int r = bm*TBM + wm*64 + 16*i + gid;
        #pragma unroll
        for (int j = 0; j < 4; j++) {
            int c = bn*TBN + wn*32 + 8*j + 2*tig;
            float bx = bias[c], by = bias[c+1];
            float v0 = acc[i][j][0] + bx;
            float v1 = acc[i][j][1] + by;
            float v2 = acc[i][j][2] + bx;
            float v3 = acc[i][j][3] + by;
            if (EPI == 1) {
                v0 = 0.5f*v0*(1.0f + erff(v0*0.70710678118654752f));
                v1 = 0.5f*v1*(1.0f + erff(v1*0.70710678118654752f));
                v2 = 0.5f*v2*(1.0f + erff(v2*0.70710678118654752f));
                v3 = 0.5f*v3*(1.0f + erff(v3*0.70710678118654752f));
            }
            float2 p0; p0.x = v0; p0.y = v1;
            float2 p1; p1.x = v2; p1.y = v3;
            *(float2*)&C[(size_t)r*N + c]       = p0;
            *(float2*)&C[(size_t)(r+8)*N + c]   = p1;
        }
    }
}

// ---------------- fused attention v6: online softmax + staged hi/lo ----------
// 32 q rows/block, grid (16,H,B), 256 threads, 64-key chunks, single pass.
#define ATTN6_SMEM (27072*4)

__global__ __launch_bounds__(256)
void attn6_kernel(const float* __restrict__ qkv,
                  const int* __restrict__ batters, const int* __restrict__ bowlers,
                  const float* __restrict__ rec_s, const float* __restrict__ bow_s,
                  const float* __restrict__ bat_s, int layer,
                  float* __restrict__ Og)
{
    extern __shared__ float sm[];
    float* Qhi = sm;
    float* Qlo = sm + 2176;
    float* Khi = sm + 4352;
    float* Klo = sm + 8704;
    float* Vhi = sm + 13056;
    float* Vlo = sm + 17664;
    float* Phi = sm + 22272;
    float* Plo = sm + 24448;
    float* Mp  = sm + 26624;
    float* Sp  = sm + 26752;
    int*   ib  = (int*)(sm + 26880);
    int* bowQ = ib;       int* batQ = ib + 32;
    int* bowK = ib + 64;  int* batK = ib + 128;

    int qt = blockIdx.x, h = blockIdx.y, b = blockIdx.z;
    int tid = threadIdx.x;
    int q0 = qt*32;
    int w = tid >> 5, lane = tid & 31;
    int gid = lane >> 2, tig = lane & 3;
    int mi = w >> 2, nq = w & 3;
    int r1 = mi*16 + gid, r2 = r1 + 8;

    const float* Q  = qkv;
    const float* Kg = qkv + Dc;
    const float* Vg = qkv + 2*Dc;

    #pragma unroll
    for (int it = 0; it < 2; ++it) {
        int idx = tid + it*256;
        int q = idx >> 4, d4 = idx & 15;
        float4 v = *(const float4*)&Q[(size_t)(b*Tc + q0 + q)*QP + h*HDc + d4*4];
        uint32_t h0,l0,h1,l1,h2,l2,h3,l3;
        tf32_split(v.x, h0, l0); tf32_split(v.y, h1, l1);
        tf32_split(v.z, h2, l2); tf32_split(v.w, h3, l3);
        float4 hv, lv;
        hv.x = __uint_as_float(h0); hv.y = __uint_as_float(h1);
        hv.z = __uint_as_float(h2); hv.w = __uint_as_float(h3);
        lv.x = __uint_as_float(l0); lv.y = __uint_as_float(l1);
        lv.z = __uint_as_float(l2); lv.w = __uint_as_float(l3);
        *(float4*)&Qhi[q*68 + d4*4] = hv;
        *(float4*)&Qlo[q*68 + d4*4] = lv;
    }
    if (tid < 32) {
        int qg = q0 + tid;
        bowQ[tid] = (qg < Sc) ? bowlers[b*Sc + qg] : -1;
        batQ[tid] = (qg < Sc) ? batters[b*Sc + qg] : -1;
    }

    int ktmax = (q0 + 32 + 63) >> 6;
    const float scl  = 0.125f;
    const float recw = rec_s[layer];
    const float boww = bow_s[layer];
    const float batw = bat_s[layer];

    int qg1 = q0 + r1, qg2 = q0 + r2;

    float oacc[2][4] = {{0,0,0,0},{0,0,0,0}};
    float mrun1 = -1e30f, mrun2 = -1e30f;
    float srun1 = 0.f,    srun2 = 0.f;

    for (int kt = 0; kt < ktmax; ++kt) {
        int k0 = kt << 6;

        #pragma unroll
        for (int it = 0; it < 4; ++it) {
            int idx = tid + it*256;
            int kk = idx >> 4, d4 = idx & 15;
            float4 v = *(const float4*)&Kg[(size_t)(b*Tc + k0 + kk)*QP + h*HDc + d4*4];
            uint32_t h0,l0,h1,l1,h2,l2,h3,l3;
            tf32_split(v.x, h0, l0); tf32_split(v.y, h1, l1);
            tf32_split(v.z, h2, l2); tf32_split(v.w, h3, l3);
            float4 hv, lv;
            hv.x = __uint_as_float(h0); hv.y = __uint_as_float(h1);
            hv.z = __uint_as_float(h2); hv.w = __uint_as_float(h3);
            lv.x = __uint_as_float(l0); lv.y = __uint_as_float(l1);
            lv.z = __uint_as_float(l2); lv.w = __uint_as_float(l3);
            *(float4*)&Khi[kk*68 + d4*4] = hv;
            *(float4*)&Klo[kk*68 + d4*4] = lv;
        }
        if (tid < 64) {
            int kg = k0 + tid;
            bowK[tid] = (kg < Sc) ? bowlers[b*Sc + kg] : -2;
            batK[tid] = (kg < Sc) ? batters[b*Sc + kg] : -2;
        }
        __syncthreads();

        float acc[2][4] = {{0,0,0,0},{0,0,0,0}};
        #pragma unroll
        for (int kc = 0; kc < 8; ++kc) {
            int ra = r1*68 + kc*8 + tig;
            uint32_t ah0 = __float_as_uint(Qhi[ra]);
            uint32_t ah1 = __float_as_uint(Qhi[ra + 8*68]);
            uint32_t ah2 = __float_as_uint(Qhi[ra + 4]);
            uint32_t ah3 = __float_as_uint(Qhi[ra + 8*68 + 4]);
            uint32_t al0 = __float_as_uint(Qlo[ra]);
            uint32_t al1 = __float_as_uint(Qlo[ra + 8*68]);
            uint32_t al2 = __float_as_uint(Qlo[ra + 4]);
            uint32_t al3 = __float_as_uint(Qlo[ra + 8*68 + 4]);
            #pragma unroll
            for (int j = 0; j < 2; ++j) {
                int rb = (nq*16 + j*8 + gid)*68 + kc*8 + tig;
                uint32_t bh0 = __float_as_uint(Khi[rb]);
                uint32_t bh1 = __float_as_uint(Khi[rb + 4]);
                uint32_t bl0 = __float_as_uint(Klo[rb]);
                uint32_t bl1 = __float_as_uint(Klo[rb + 4]);
                MMA_TF32(acc[j], ah0, ah1, ah2, ah3, bl0, bl1);
                MMA_TF32(acc[j], al0, al1, al2, al3, bh0, bh1);
                MMA_TF32(acc[j], ah0, ah1, ah2, ah3, bh0, bh1);
            }
        }

        #pragma unroll
        for (int it = 0; it < 4; ++it) {
            int idx = tid + it*256;
            int kk = idx >> 4, d4 = idx & 15;
            float4 v = *(const float4*)&Vg[(size_t)(b*Tc + k0 + kk)*QP + h*HDc + d4*4];
            uint32_t h0,l0,h1,l1,h2,l2,h3,l3;
            tf32_split(v.x, h0, l0); tf32_split(v.y, h1, l1);
            tf32_split(v.z, h2, l2); tf32_split(v.w, h3, l3);
            float4 hv, lv;
            hv.x = __uint_as_float(h0); hv.y = __uint_as_float(h1);
            hv.z = __uint_as_float(h2); hv.w = __uint_as_float(h3);
            lv.x = __uint_as_float(l0); lv.y = __uint_as_float(l1);
            lv.z = __uint_as_float(l2); lv.w = __uint_as_float(l3);
            *(float4*)&Vhi[kk*72 + d4*4] = hv;
            *(float4*)&Vlo[kk*72 + d4*4] = lv;
        }

        float sv[2][4];
        int bq1 = bowQ[r1], aq1 = batQ[r1];
        int bq2 = bowQ[r2], aq2 = batQ[r2];
        #pragma unroll
        for (int j = 0; j < 2; ++j) {
            int kl = nq*16 + j*8 + 2*tig;
            int kg = k0 + kl;
            float s00 = acc[j][0]*scl, s01 = acc[j][1]*scl;
            float s10 = acc[j][2]*scl, s11 = acc[j][3]*scl;
            if (h == 0) {
                s00 += recw * (float)kg     * (1.0f/512.0f);
                s01 += recw * (float)(kg+1) * (1.0f/512.0f);
                s10 += recw * (float)kg     * (1.0f/512.0f);
                s11 += recw * (float)(kg+1) * (1.0f/512.0f);
            } else if (h == 1) {
                int k1b = bowK[kl], k2b = bowK[kl+1];
                if (qg1 == Sc || kg   == Sc || bq1 == k1b) s00 += boww;
                if (qg1 == Sc || kg+1 == Sc || bq1 == k2b) s01 += boww;
                if (qg2 == Sc || kg   == Sc || bq2 == k1b) s10 += boww;
                if (qg2 == Sc || kg+1 == Sc || bq2 == k2b) s11 += boww;
            } else if (h == 2) {
                int k1a = batK[kl], k2a = batK[kl+1];
                if (qg1 == Sc || kg   == Sc || aq1 == k1a) s00 += batw;
                if (qg1 == Sc || kg+1 == Sc || aq1 == k2a) s01 += batw;
                if (qg2 == Sc || kg   == Sc || aq2 == k1a) s10 += batw;
                if (qg2 == Sc || kg+1 == Sc || aq2 == k2a) s11 += batw;
            }
            if (kg   > qg1) s00 = -1e30f;
            if (kg+1 > qg1) s01 = -1e30f;
            if (kg   > qg2) s10 = -1e30f;
            if (kg+1 > qg2) s11 = -1e30f;
            sv[j][0] = s00; sv[j][1] = s01; sv[j][2] = s10; sv[j][3] = s11;
        }

        float rm1 = fmaxf(fmaxf(sv[0][0], sv[0][1]), fmaxf(sv[1][0], sv[1][1]));
        float rm2 = fmaxf(fmaxf(sv[0][2], sv[0][3]), fmaxf(sv[1][2], sv[1][3]));
        rm1 = fmaxf(rm1, __shfl_xor_sync(0xffffffffu, rm1, 1));
        rm1 = fmaxf(rm1, __shfl_xor_sync(0xffffffffu, rm1, 2));
        rm2 = fmaxf(rm2, __shfl_xor_sync(0xffffffffu, rm2, 1));
        rm2 = fmaxf(rm2, __shfl_xor_sync(0xffffffffu, rm2, 2));
        if (tig == 0) { Mp[r1*4 + nq] = rm1; Mp[r2*4 + nq] = rm2; }
        __syncthreads();

        float4 m4a = *(const float4*)&Mp[r1*4];
        float4 m4b = *(const float4*)&Mp[r2*4];
        float mc1 = fmaxf(fmaxf(m4a.x, m4a.y), fmaxf(m4a.z, m4a.w));
        float mc2 = fmaxf(fmaxf(m4b.x, m4b.y), fmaxf(m4b.z, m4b.w));
        float mnew1 = fmaxf(mrun1, mc1);
        float mnew2 = fmaxf(mrun2, mc2);
        float f1 = __expf(mrun1 - mnew1);
        float f2 = __expf(mrun2 - mnew2);

        float ps1 = 0.f, ps2 = 0.f;
        #pragma unroll
        for (int j = 0; j < 2; ++j) {
            int col = nq*16 + j*8 + 2*tig;
            float e00 = __expf(sv[j][0] - mnew1);
            float e01 = __expf(sv[j][1] - mnew1);
            float e10 = __expf(sv[j][2] - mnew2);
            float e11 = __expf(sv[j][3] - mnew2);
            ps1 += e00 + e01;
            ps2 += e10 + e11;
            uint32_t h0,l0,h1,l1;
            tf32_split(e00, h0, l0); tf32_split(e01, h1, l1);
            float2 hv, lv;
            hv.x = __uint_as_float(h0); hv.y = __uint_as_float(h1);
            lv.x = __uint_as_float(l0); lv.y = __uint_as_float(l1);
            *(float2*)&Phi[r1*68 + col] = hv;
            *(float2*)&Plo[r1*68 + col] = lv;
            tf32_split(e10, h0, l0); tf32_split(e11, h1, l1);
            hv.x = __uint_as_float(h0); hv.y = __uint_as_float(h1);
            lv.x = __uint_as_float(l0); lv.y = __uint_as_float(l1);
            *(float2*)&Phi[r2*68 + col] = hv;
            *(float2*)&Plo[r2*68 + col] = lv;
        }
        ps1 += __shfl_xor_sync(0xffffffffu, ps1, 1);
        ps1 += __shfl_xor_sync(0xffffffffu, ps1, 2);
        ps2 += __shfl_xor_sync(0xffffffffu, ps2, 1);
        ps2 += __shfl_xor_sync(0xffffffffu, ps2, 2);
        if (tig == 0) { Sp[r1*4 + nq] = ps1; Sp[r2*4 + nq] = ps2; }

        oacc[0][0] *= f1; oacc[0][1] *= f1; oacc[1][0] *= f1; oacc[1][1] *= f1;
        oacc[0][2] *= f2; oacc[0][3] *= f2; oacc[1][2] *= f2; oacc[1][3] *= f2;
        mrun1 = mnew1; mrun2 = mnew2;
        __syncthreads();

        float4 s4a = *(const float4*)&Sp[r1*4];
        float4 s4b = *(const float4*)&Sp[r2*4];
        srun1 = srun1*f1 + (s4a.x + s4a.y + s4a.z + s4a.w);
        srun2 = srun2*f2 + (s4b.x + s4b.y + s4b.z + s4b.w);

        #pragma unroll
        for (int kc = 0; kc < 8; ++kc) {
            int pa1 = r1*68 + kc*8 + tig;
            int pa2 = r2*68 + kc*8 + tig;
            uint32_t ah0 = __float_as_uint(Phi[pa1]);
            uint32_t ah1 = __float_as_uint(Phi[pa2]);
            uint32_t ah2 = __float_as_uint(Phi[pa1 + 4]);
            uint32_t ah3 = __float_as_uint(Phi[pa2 + 4]);
            uint32_t al0 = __float_as_uint(Plo[pa1]);
            uint32_t al1 = __float_as_uint(Plo[pa2]);
            uint32_t al2 = __float_as_uint(Plo[pa1 + 4]);
            uint32_t al3 = __float_as_uint(Plo[pa2 + 4]);
            #pragma unroll
            for (int j = 0; j < 2; ++j) {
                int n0 = (nq*2 + j)*8;
                int vb0 = (kc*8 + tig    )*72 + n0 + gid;
                int vb1 = (kc*8 + tig + 4)*72 + n0 + gid;
                uint32_t bh0 = __float_as_uint(Vhi[vb0]);
                uint32_t bh1 = __float_as_uint(Vhi[vb1]);
                uint32_t bl0 = __float_as_uint(Vlo[vb0]);
                uint32_t bl1 = __float_as_uint(Vlo[vb1]);
                MMA_TF32(oacc[j], ah0, ah1, ah2, ah3, bl0, bl1);
                MMA_TF32(oacc[j], al0, al1, al2, al3, bh0, bh1);
                MMA_TF32(oacc[j], ah0, ah1, ah2, ah3, bh0, bh1);
            }
        }
    }

    float inv1 = 1.0f / srun1;
    float inv2 = 1.0f / srun2;
    #pragma unroll
    for (int j = 0; j < 2; ++j) {
        int col = (nq*2 + j)*8 + 2*tig;
        float2 o1; o1.x = oacc[j][0]*inv1; o1.y = oacc[j][1]*inv1;
        float2 o2; o2.x = oacc[j][2]*inv2; o2.y = oacc[j][3]*inv2;
        *(float2*)&Og[(size_t)(b*Tc + q0 + r1)*Dc + h*HDc + col] = o1;
        *(float2*)&Og[(size_t)(b*Tc + q0 + r2)*Dc + h*HDc + col] = o2;
    }
}

// ---------------- residual add + LayerNorm (in-place on x) ------------------
__global__ __launch_bounds__(512)
void add_ln_kernel(float* __restrict__ x, const float* __restrict__ r,
                   const float* __restrict__ g, const float* __restrict__ be)
{
    int tok = blockIdx.x;
    int j = threadIdx.x;
    float v = x[(size_t)tok*Dc + j] + r[(size_t)tok*Dc + j];

    __shared__ float s1[16], s2[16];
    float a = v, b2 = v*v;
    #pragma unroll
    for (int o = 16; o; o >>= 1) {
        a  += __shfl_xor_sync(0xffffffffu, a, o);
        b2 += __shfl_xor_sync(0xffffffffu, b2, o);
    }
    int w = j >> 5, lane = j & 31;
    if (lane == 0) { s1[w] = a; s2[w] = b2; }
    __syncthreads();
    if (j < 16) {
        a = s1[j]; b2 = s2[j];
        #pragma unroll
        for (int o = 8; o; o >>= 1) {
            a  += __shfl_xor_sync(0x0000ffffu, a, o);
            b2 += __shfl_xor_sync(0x0000ffffu, b2, o);
        }
        if (j == 0) { s1[0] = a; s2[0] = b2; }
    }
    __syncthreads();
    float mu  = s1[0] * (1.0f/512.0f);
    float var = s2[0] * (1.0f/512.0f) - mu*mu;
    float y = (v - mu) * rsqrtf(var + 1e-5f) * g[j] + be[j];
    x[(size_t)tok*Dc + j] = y;
}

// ---------------- output head: out[b] = x[b, T-1] @ Wout + bout -------------
__global__ __launch_bounds__(512)
void out_kernel(const float* __restrict__ x, const float* __restrict__ Wout,
                const float* __restrict__ bout, float* __restrict__ out)
{
    int b = blockIdx.x;
    int n = threadIdx.x;
    __shared__ float xs[512];
    xs[n] = x[(size_t)(b*Tc + Tc - 1)*Dc + n];
    __syncthreads();
    float acc = bout[n];
    #pragma unroll 8
    for (int d = 0; d < Dc; ++d)
        acc += xs[d] * Wout[(size_t)d*Dc + n];
    out[b*Dc + n] = acc;
}

// ---------------- launcher ---------------------------------------------------
extern "C" void kernel_launch(void* const* d_in, const int* in_sizes, int n_in,
                              void* d_out, int out_size)
{
    const float* runs    = (const float*)d_in[0];
    const float* wickets = (const float*)d_in[1];
    const float* overs   = (const float*)d_in[2];
    const int*   batters = (const int*)  d_in[3];
    const int*   bowlers = (const int*)  d_in[4];
    const float* pemb    = (const float*)d_in[5];
    const float* Wf      = (const float*)d_in[6];
    const float* bf      = (const float*)d_in[7];
    const float* qtok    = (const float*)d_in[8];
    const float* Wq      = (const float*)d_in[9];
    const float* bq      = (const float*)d_in[10];
    const float* Wk      = (const float*)d_in[11];
    const float* bk      = (const float*)d_in[12];
    const float* Wv      = (const float*)d_in[13];
    const float* bv      = (const float*)d_in[14];
    const float* Wo      = (const float*)d_in[15];
    const float* bo      = (const float*)d_in[16];
    const float* rec_s   = (const float*)d_in[17];
    const float* bow_s   = (const float*)d_in[18];
    const float* bat_s   = (const float*)d_in[19];
    const float* W1      = (const float*)d_in[20];
    const float* b1      = (const float*)d_in[21];
    const float* W2      = (const float*)d_in[22];
    const float* b2      = (const float*)d_in[23];
    const float* g1      = (const float*)d_in[24];
    const float* be1     = (const float*)d_in[25];
    const float* g2      = (const float*)d_in[26];
    const float* be2     = (const float*)d_in[27];
    const float* Wout    = (const float*)d_in[28];
    const float* bout    = (const float*)d_in[29];
    float* out = (float*)d_out;

    float *x_, *att_, *tmp_, *ff_, *wqkv_, *bqkv_;
    cudaGetSymbolAddress((void**)&x_,    g_x);
    cudaGetSymbolAddress((void**)&att_,  g_att);
    cudaGetSymbolAddress((void**)&tmp_,  g_tmp);
    cudaGetSymbolAddress((void**)&ff_,   g_ff);
    cudaGetSymbolAddress((void**)&wqkv_, g_wqkv);
    cudaGetSymbolAddress((void**)&bqkv_, g_bqkv);

    cudaFuncSetAttribute(attn6_kernel,
                         cudaFuncAttributeMaxDynamicSharedMemorySize, ATTN6_SMEM);
    cudaFuncSetAttribute(tgemm_kernel<0>,
                         cudaFuncAttributeMaxDynamicSharedMemorySize, TGEMM_SMEM);
    cudaFuncSetAttribute(tgemm_kernel<1>,
                         cudaFuncAttributeMaxDynamicSharedMemorySize, TGEMM_SMEM);

    pack_qkv_kernel<<<Lc*Dc, 512>>>(Wq, Wk, Wv, wqkv_);
    pack_bqkv_kernel<<<Lc, 512>>>(bq, bk, bv, bqkv_);

    embed_kernel<<<Bc*Tc, 512>>>(runs, wickets, overs, batters, bowlers,
                                 pemb, Wf, bf, qtok, x_);

    dim3 g512 (Dc/TBN,   Mc/TBM);   // (4, 128)
    dim3 gQKV (QP/TBN,   Mc/TBM);   // (12, 128)
    dim3 g2048(DFFc/TBN, Mc/TBM);   // (16, 128)
    dim3 gattn(16, Hc, Bc);

    for (int l = 0; l < Lc; ++l) {
        tgemm_kernel<0><<<gQKV, 256, TGEMM_SMEM>>>(x_, wqkv_ + (size_t)l*Dc*QP,
                                                   bqkv_ + l*QP, ff_, Mc, QP, Dc);

        attn6_kernel<<<gattn, 256, ATTN6_SMEM>>>(ff_, batters, bowlers,
                                                 rec_s, bow_s, bat_s, l, att_);

        tgemm_kernel<0><<<g512, 256, TGEMM_SMEM>>>(att_, Wo + (size_t)l*Dc*Dc,
                                                   bo + l*Dc, tmp_, Mc, Dc, Dc);
        add_ln_kernel<<<Mc, 512>>>(x_, tmp_, g1 + l*Dc, be1 + l*Dc);

        tgemm_kernel<1><<<g2048, 256, TGEMM_SMEM>>>(x_, W1 + (size_t)l*Dc*DFFc,
                                                    b1 + l*DFFc, ff_, Mc, DFFc, Dc);
        tgemm_kernel<0><<<g512, 256, TGEMM_SMEM>>>(ff_, W2 + (size_t)l*DFFc*Dc,
                                                   b2 + l*Dc, tmp_, Mc, Dc, DFFc);
        add_ln_kernel<<<Mc, 512>>>(x_, tmp_, g2 + l*Dc, be2 + l*Dc);
    }

    out_kernel<<<Bc, 512>>>(x_, Wout, bout, out);
}

// round 10
// speedup vs baseline: 1.4980x; 1.0512x over previous
#include <cuda_runtime.h>
#include <cuda_bf16.h>
#include <math_constants.h>
#include <cstdint>

// Problem constants
#define Bc   32
#define Sc   511
#define Tc   512
#define Dc   512
#define Hc   8
#define HDc  64
#define Lc   4
#define PDc  32
#define FDc  448     // D - 2*PD
#define DFFc 2048
#define Mc   (Bc*Tc) // 16384 tokens
#define QP   1536    // qkv combined pitch

// ---------------- scratch (device globals; no allocation allowed) ----------
__device__ float g_x   [Mc*Dc];
__device__ float g_att [Mc*Dc];
__device__ float g_tmp [Mc*Dc];
__device__ float g_ff  [Mc*DFFc];      // doubles as qkv buffer [Mc][1536]
__device__ float g_wqkv[Lc*Dc*QP];
__device__ float g_bqkv[Lc*QP];

// ---------------- weight packing --------------------------------------------
__global__ __launch_bounds__(512)
void pack_qkv_kernel(const float* __restrict__ Wq, const float* __restrict__ Wk,
                     const float* __restrict__ Wv, float* __restrict__ Wqkv)
{
    int lk = blockIdx.x;
    int j  = threadIdx.x;
    size_t src = (size_t)lk*Dc + j;
    size_t dst = (size_t)lk*QP + j;
    Wqkv[dst        ] = Wq[src];
    Wqkv[dst + Dc   ] = Wk[src];
    Wqkv[dst + 2*Dc ] = Wv[src];
}
__global__ __launch_bounds__(512)
void pack_bqkv_kernel(const float* __restrict__ bq, const float* __restrict__ bk,
                      const float* __restrict__ bv, float* __restrict__ bqkv)
{
    int l = blockIdx.x;
    int j = threadIdx.x;
    bqkv[l*QP + j       ] = bq[l*Dc + j];
    bqkv[l*QP + j + Dc  ] = bk[l*Dc + j];
    bqkv[l*QP + j + 2*Dc] = bv[l*Dc + j];
}

// ---------------- embedding + positional encoding ---------------------------
__global__ void embed_kernel(const float* __restrict__ runs,
                             const float* __restrict__ wickets,
                             const float* __restrict__ overs,
                             const int*   __restrict__ batters,
                             const int*   __restrict__ bowlers,
                             const float* __restrict__ pemb,
                             const float* __restrict__ Wf,
                             const float* __restrict__ bf,
                             const float* __restrict__ qtok,
                             float* __restrict__ x)
{
    int bt = blockIdx.x;
    int b  = bt / Tc;
    int t  = bt % Tc;
    int j  = threadIdx.x;

    float val;
    if (t < Sc) {
        if (j < FDc) {
            float r = runs   [b*Sc + t];
            float w = wickets[b*Sc + t];
            float o = overs  [b*Sc + t];
            val = r*Wf[j] + w*Wf[FDc + j] + o*Wf[2*FDc + j] + bf[j];
        } else if (j < FDc + PDc) {
            val = pemb[batters[b*Sc + t]*PDc + (j - FDc)];
        } else {
            val = pemb[bowlers[b*Sc + t]*PDc + (j - FDc - PDc)];
        }
    } else {
        val = qtok[j];
    }
    int   i2  = j & ~1;
    float dv  = expf((float)i2 * -0.0179889460390111f);
    float ang = (float)t * dv;
    val += (j & 1) ? cosf(ang) : sinf(ang);
    x[(b*Tc + t)*Dc + j] = val;
}

// ---------------- helpers -----------------------------------------------------
__device__ __forceinline__ uint32_t smem_u32(const void* p) {
    return (uint32_t)__cvta_generic_to_shared(p);
}
#define MMA_TF32(ACC, A0,A1,A2,A3, B0,B1) \
    asm volatile( \
        "mma.sync.aligned.m16n8k8.row.col.f32.tf32.tf32.f32 " \
        "{%0,%1,%2,%3}, {%4,%5,%6,%7}, {%8,%9}, {%0,%1,%2,%3};\n" \
        : "+f"((ACC)[0]), "+f"((ACC)[1]), "+f"((ACC)[2]), "+f"((ACC)[3]) \
        : "r"(A0), "r"(A1), "r"(A2), "r"(A3), "r"(B0), "r"(B1))
__device__ __forceinline__ uint32_t tf32_hi(float v) {
    uint32_t r; asm("cvt.rna.tf32.f32 %0, %1;" : "=r"(r) : "f"(v)); return r;
}
__device__ __forceinline__ void tf32_split(float v, uint32_t& hi, uint32_t& lo) {
    hi = tf32_hi(v);
    lo = tf32_hi(v - __uint_as_float(hi));
}

// ---------------- tf32 tensor-core GEMM, 3-stage cp.async, 1 sync/chunk ------
#define TBM 128
#define TBN 128
#define TBK 32
#define AST 36
#define BST 136
#define TG_ST 3
#define TGEMM_SMEM ((TG_ST*TBM*AST + TG_ST*32*BST)*4)

__device__ __forceinline__ void tg_load_stage(
    const float* __restrict__ A, const float* __restrict__ W,
    float* __restrict__ As, float* __restrict__ Bs,
    int bm, int bn, int k0, int K, int N, int tid)
{
    int ar = tid >> 3, aq = tid & 7;
    const float* ap = A + (size_t)(bm*TBM + ar)*K + k0 + aq*4;
    uint32_t ad = smem_u32(As + ar*AST + aq*4);
    #pragma unroll
    for (int i = 0; i < 4; i++) {
        asm volatile("cp.async.cg.shared.global [%0], [%1], 16;\n"
                     :: "r"(ad + i*32*AST*4), "l"(ap + (size_t)i*32*K));
    }
    int br = tid >> 5, bq = tid & 31;
    const float* bp = W + (size_t)(k0 + br)*N + bn*TBN + bq*4;
    uint32_t bd = smem_u32(Bs + br*BST + bq*4);
    #pragma unroll
    for (int i = 0; i < 4; i++) {
        asm volatile("cp.async.cg.shared.global [%0], [%1], 16;\n"
                     :: "r"(bd + i*8*BST*4), "l"(bp + (size_t)i*8*N));
    }
    asm volatile("cp.async.commit_group;\n");
}

template<int EPI>
__global__ __launch_bounds__(256, 2)
void tgemm_kernel(const float* __restrict__ A, const float* __restrict__ W,
                  const float* __restrict__ bias, float* __restrict__ C,
                  int M, int N, int K)
{
    extern __shared__ float sm[];
    float* As = sm;
    float* Bs = sm + TG_ST*TBM*AST;

    int tid = threadIdx.x;
    int bm = blockIdx.y, bn = blockIdx.x;
    int w = tid >> 5, lane = tid & 31;
    int gid = lane >> 2, tig = lane & 3;
    int wm = w >> 2, wn = w & 3;

    float acc[4][4][4];
    #pragma unroll
    for (int i = 0; i < 4; i++)
        #pragma unroll
        for (int j = 0; j < 4; j++)
            #pragma unroll
            for (int r = 0; r < 4; r++) acc[i][j][r] = 0.f;

    int nkt = K / TBK;
    tg_load_stage(A, W, As, Bs, bm, bn, 0, K, N, tid);
    if (nkt > 1)
        tg_load_stage(A, W, As + TBM*AST, Bs + 32*BST, bm, bn, TBK, K, N, tid);

    for (int kt = 0; kt < nkt; ++kt) {
        if (kt + 1 < nkt) asm volatile("cp.async.wait_group 1;\n");
        else              asm volatile("cp.async.wait_group 0;\n");
        __syncthreads();
        if (kt + 2 < nkt) {
            int nxt = (kt + 2) % TG_ST;
            tg_load_stage(A, W, As + nxt*TBM*AST, Bs + nxt*32*BST,
                          bm, bn, (kt+2)*TBK, K, N, tid);
        }

        const float* Asc = As + (kt % TG_ST)*TBM*AST;
        const float* Bsc = Bs + (kt % TG_ST)*32*BST;

        #pragma unroll
        for (int kc = 0; kc < 4; ++kc) {
            uint32_t a[4][4], b[4][2];
            #pragma unroll
            for (int i = 0; i < 4; i++) {
                int r0 = wm*64 + 16*i + gid;
                a[i][0] = __float_as_uint(Asc[(r0    )*AST + kc*8 + tig    ]);
                a[i][1] = __float_as_uint(Asc[(r0 + 8)*AST + kc*8 + tig    ]);
                a[i][2] = __float_as_uint(Asc[(r0    )*AST + kc*8 + tig + 4]);
                a[i][3] = __float_as_uint(Asc[(r0 + 8)*AST + kc*8 + tig + 4]);
            }
            #pragma unroll
            for (int j = 0; j < 4; j++) {
                int c0 = wn*32 + 8*j + gid;
                b[j][0] = __float_as_uint(Bsc[(kc*8 + tig    )*BST + c0]);
                b[j][1] = __float_as_uint(Bsc[(kc*8 + tig + 4)*BST + c0]);
            }
            #pragma unroll
            for (int i = 0; i < 4; i++)
                #pragma unroll
                for (int j = 0; j < 4; j++)
                    MMA_TF32(acc[i][j], a[i][0], a[i][1], a[i][2], a[i][3],
                             b[j][0], b[j][1]);
        }
    }

    #pragma unroll
    for (int i = 0; i < 4; i++) {
        int r = bm*TBM + wm*64 + 16*i + gid;
        #pragma unroll
        for (int j = 0; j < 4; j++) {
            int c = bn*TBN + wn*32 + 8*j + 2*tig;
            float bx = bias[c], by = bias[c+1];
            float v0 = acc[i][j][0] + bx;
            float v1 = acc[i][j][1] + by;
            float v2 = acc[i][j][2] + bx;
            float v3 = acc[i][j][3] + by;
            if (EPI == 1) {
                v0 = 0.5f*v0*(1.0f + erff(v0*0.70710678118654752f));
                v1 = 0.5f*v1*(1.0f + erff(v1*0.70710678118654752f));
                v2 = 0.5f*v2*(1.0f + erff(v2*0.70710678118654752f));
                v3 = 0.5f*v3*(1.0f + erff(v3*0.70710678118654752f));
            }
            float2 p0; p0.x = v0; p0.y = v1;
            float2 p1; p1.x = v2; p1.y = v3;
            *(float2*)&C[(size_t)r*N + c]       = p0;
            *(float2*)&C[(size_t)(r+8)*N + c]   = p1;
        }
    }
}

// ---------------- fused attention v6: online softmax + staged hi/lo ----------
#define ATTN6_SMEM (27072*4)

__global__ __launch_bounds__(256)
void attn6_kernel(const float* __restrict__ qkv,
                  const int* __restrict__ batters, const int* __restrict__ bowlers,
                  const float* __restrict__ rec_s, const float* __restrict__ bow_s,
                  const float* __restrict__ bat_s, int layer,
                  float* __restrict__ Og)
{
    extern __shared__ float sm[];
    float* Qhi = sm;
    float* Qlo = sm + 2176;
    float* Khi = sm + 4352;
    float* Klo = sm + 8704;
    float* Vhi = sm + 13056;
    float* Vlo = sm + 17664;
    float* Phi = sm + 22272;
    float* Plo = sm + 24448;
    float* Mp  = sm + 26624;
    float* Sp  = sm + 26752;
    int*   ib  = (int*)(sm + 26880);
    int* bowQ = ib;       int* batQ = ib + 32;
    int* bowK = ib + 64;  int* batK = ib + 128;

    int qt = blockIdx.x, h = blockIdx.y, b = blockIdx.z;
    int tid = threadIdx.x;
    int q0 = qt*32;
    int w = tid >> 5, lane = tid & 31;
    int gid = lane >> 2, tig = lane & 3;
    int mi = w >> 2, nq = w & 3;
    int r1 = mi*16 + gid, r2 = r1 + 8;

    const float* Q  = qkv;
    const float* Kg = qkv + Dc;
    const float* Vg = qkv + 2*Dc;

    #pragma unroll
    for (int it = 0; it < 2; ++it) {
        int idx = tid + it*256;
        int q = idx >> 4, d4 = idx & 15;
        float4 v = *(const float4*)&Q[(size_t)(b*Tc + q0 + q)*QP + h*HDc + d4*4];
        uint32_t h0,l0,h1,l1,h2,l2,h3,l3;
        tf32_split(v.x, h0, l0); tf32_split(v.y, h1, l1);
        tf32_split(v.z, h2, l2); tf32_split(v.w, h3, l3);
        float4 hv, lv;
        hv.x = __uint_as_float(h0); hv.y = __uint_as_float(h1);
        hv.z = __uint_as_float(h2); hv.w = __uint_as_float(h3);
        lv.x = __uint_as_float(l0); lv.y = __uint_as_float(l1);
        lv.z = __uint_as_float(l2); lv.w = __uint_as_float(l3);
        *(float4*)&Qhi[q*68 + d4*4] = hv;
        *(float4*)&Qlo[q*68 + d4*4] = lv;
    }
    if (tid < 32) {
        int qg = q0 + tid;
        bowQ[tid] = (qg < Sc) ? bowlers[b*Sc + qg] : -1;
        batQ[tid] = (qg < Sc) ? batters[b*Sc + qg] : -1;
    }

    int ktmax = (q0 + 32 + 63) >> 6;
    const float scl  = 0.125f;
    const float recw = rec_s[layer];
    const float boww = bow_s[layer];
    const float batw = bat_s[layer];

    int qg1 = q0 + r1, qg2 = q0 + r2;

    float oacc[2][4] = {{0,0,0,0},{0,0,0,0}};
    float mrun1 = -1e30f, mrun2 = -1e30f;
    float srun1 = 0.f,    srun2 = 0.f;

    for (int kt = 0; kt < ktmax; ++kt) {
        int k0 = kt << 6;

        #pragma unroll
        for (int it = 0; it < 4; ++it) {
            int idx = tid + it*256;
            int kk = idx >> 4, d4 = idx & 15;
            float4 v = *(const float4*)&Kg[(size_t)(b*Tc + k0 + kk)*QP + h*HDc + d4*4];
            uint32_t h0,l0,h1,l1,h2,l2,h3,l3;
            tf32_split(v.x, h0, l0); tf32_split(v.y, h1, l1);
            tf32_split(v.z, h2, l2); tf32_split(v.w, h3, l3);
            float4 hv, lv;
            hv.x = __uint_as_float(h0); hv.y = __uint_as_float(h1);
            hv.z = __uint_as_float(h2); hv.w = __uint_as_float(h3);
            lv.x = __uint_as_float(l0); lv.y = __uint_as_float(l1);
            lv.z = __uint_as_float(l2); lv.w = __uint_as_float(l3);
            *(float4*)&Khi[kk*68 + d4*4] = hv;
            *(float4*)&Klo[kk*68 + d4*4] = lv;
        }
        if (tid < 64) {
            int kg = k0 + tid;
            bowK[tid] = (kg < Sc) ? bowlers[b*Sc + kg] : -2;
            batK[tid] = (kg < Sc) ? batters[b*Sc + kg] : -2;
        }
        __syncthreads();

        float acc[2][4] = {{0,0,0,0},{0,0,0,0}};
        #pragma unroll
        for (int kc = 0; kc < 8; ++kc) {
            int ra = r1*68 + kc*8 + tig;
            uint32_t ah0 = __float_as_uint(Qhi[ra]);
            uint32_t ah1 = __float_as_uint(Qhi[ra + 8*68]);
            uint32_t ah2 = __float_as_uint(Qhi[ra + 4]);
            uint32_t ah3 = __float_as_uint(Qhi[ra + 8*68 + 4]);
            uint32_t al0 = __float_as_uint(Qlo[ra]);
            uint32_t al1 = __float_as_uint(Qlo[ra + 8*68]);
            uint32_t al2 = __float_as_uint(Qlo[ra + 4]);
            uint32_t al3 = __float_as_uint(Qlo[ra + 8*68 + 4]);
            #pragma unroll
            for (int j = 0; j < 2; ++j) {
                int rb = (nq*16 + j*8 + gid)*68 + kc*8 + tig;
                uint32_t bh0 = __float_as_uint(Khi[rb]);
                uint32_t bh1 = __float_as_uint(Khi[rb + 4]);
                uint32_t bl0 = __float_as_uint(Klo[rb]);
                uint32_t bl1 = __float_as_uint(Klo[rb + 4]);
                MMA_TF32(acc[j], ah0, ah1, ah2, ah3, bl0, bl1);
                MMA_TF32(acc[j], al0, al1, al2, al3, bh0, bh1);
                MMA_TF32(acc[j], ah0, ah1, ah2, ah3, bh0, bh1);
            }
        }

        #pragma unroll
        for (int it = 0; it < 4; ++it) {
            int idx = tid + it*256;
            int kk = idx >> 4, d4 = idx & 15;
            float4 v = *(const float4*)&Vg[(size_t)(b*Tc + k0 + kk)*QP + h*HDc + d4*4];
            uint32_t h0,l0,h1,l1,h2,l2,h3,l3;
            tf32_split(v.x, h0, l0); tf32_split(v.y, h1, l1);
            tf32_split(v.z, h2, l2); tf32_split(v.w, h3, l3);
            float4 hv, lv;
            hv.x = __uint_as_float(h0); hv.y = __uint_as_float(h1);
            hv.z = __uint_as_float(h2); hv.w = __uint_as_float(h3);
            lv.x = __uint_as_float(l0); lv.y = __uint_as_float(l1);
            lv.z = __uint_as_float(l2); lv.w = __uint_as_float(l3);
            *(float4*)&Vhi[kk*72 + d4*4] = hv;
            *(float4*)&Vlo[kk*72 + d4*4] = lv;
        }

        float sv[2][4];
        int bq1 = bowQ[r1], aq1 = batQ[r1];
        int bq2 = bowQ[r2], aq2 = batQ[r2];
        #pragma unroll
        for (int j = 0; j < 2; ++j) {
            int kl = nq*16 + j*8 + 2*tig;
            int kg = k0 + kl;
            float s00 = acc[j][0]*scl, s01 = acc[j][1]*scl;
            float s10 = acc[j][2]*scl, s11 = acc[j][3]*scl;
            if (h == 0) {
                s00 += recw * (float)kg     * (1.0f/512.0f);
                s01 += recw * (float)(kg+1) * (1.0f/512.0f);
                s10 += recw * (float)kg     * (1.0f/512.0f);
                s11 += recw * (float)(kg+1) * (1.0f/512.0f);
            } else if (h == 1) {
                int k1b = bowK[kl], k2b = bowK[kl+1];
                if (qg1 == Sc || kg   == Sc || bq1 == k1b) s00 += boww;
                if (qg1 == Sc || kg+1 == Sc || bq1 == k2b) s01 += boww;
                if (qg2 == Sc || kg   == Sc || bq2 == k1b) s10 += boww;
                if (qg2 == Sc || kg+1 == Sc || bq2 == k2b) s11 += boww;
            } else if (h == 2) {
                int k1a = batK[kl], k2a = batK[kl+1];
                if (qg1 == Sc || kg   == Sc || aq1 == k1a) s00 += batw;
                if (qg1 == Sc || kg+1 == Sc || aq1 == k2a) s01 += batw;
                if (qg2 == Sc || kg   == Sc || aq2 == k1a) s10 += batw;
                if (qg2 == Sc || kg+1 == Sc || aq2 == k2a) s11 += batw;
            }
            if (kg   > qg1) s00 = -1e30f;
            if (kg+1 > qg1) s01 = -1e30f;
            if (kg   > qg2) s10 = -1e30f;
            if (kg+1 > qg2) s11 = -1e30f;
            sv[j][0] = s00; sv[j][1] = s01; sv[j][2] = s10; sv[j][3] = s11;
        }

        float rm1 = fmaxf(fmaxf(sv[0][0], sv[0][1]), fmaxf(sv[1][0], sv[1][1]));
        float rm2 = fmaxf(fmaxf(sv[0][2], sv[0][3]), fmaxf(sv[1][2], sv[1][3]));
        rm1 = fmaxf(rm1, __shfl_xor_sync(0xffffffffu, rm1, 1));
        rm1 = fmaxf(rm1, __shfl_xor_sync(0xffffffffu, rm1, 2));
        rm2 = fmaxf(rm2, __shfl_xor_sync(0xffffffffu, rm2, 1));
        rm2 = fmaxf(rm2, __shfl_xor_sync(0xffffffffu, rm2, 2));
        if (tig == 0) { Mp[r1*4 + nq] = rm1; Mp[r2*4 + nq] = rm2; }
        __syncthreads();

        float4 m4a = *(const float4*)&Mp[r1*4];
        float4 m4b = *(const float4*)&Mp[r2*4];
        float mc1 = fmaxf(fmaxf(m4a.x, m4a.y), fmaxf(m4a.z, m4a.w));
        float mc2 = fmaxf(fmaxf(m4b.x, m4b.y), fmaxf(m4b.z, m4b.w));
        float mnew1 = fmaxf(mrun1, mc1);
        float mnew2 = fmaxf(mrun2, mc2);
        float f1 = __expf(mrun1 - mnew1);
        float f2 = __expf(mrun2 - mnew2);

        float ps1 = 0.f, ps2 = 0.f;
        #pragma unroll
        for (int j = 0; j < 2; ++j) {
            int col = nq*16 + j*8 + 2*tig;
            float e00 = __expf(sv[j][0] - mnew1);
            float e01 = __expf(sv[j][1] - mnew1);
            float e10 = __expf(sv[j][2] - mnew2);
            float e11 = __expf(sv[j][3] - mnew2);
            ps1 += e00 + e01;
            ps2 += e10 + e11;
            uint32_t h0,l0,h1,l1;
            tf32_split(e00, h0, l0); tf32_split(e01, h1, l1);
            float2 hv, lv;
            hv.x = __uint_as_float(h0); hv.y = __uint_as_float(h1);
            lv.x = __uint_as_float(l0); lv.y = __uint_as_float(l1);
            *(float2*)&Phi[r1*68 + col] = hv;
            *(float2*)&Plo[r1*68 + col] = lv;
            tf32_split(e10, h0, l0); tf32_split(e11, h1, l1);
            hv.x = __uint_as_float(h0); hv.y = __uint_as_float(h1);
            lv.x = __uint_as_float(l0); lv.y = __uint_as_float(l1);
            *(float2*)&Phi[r2*68 + col] = hv;
            *(float2*)&Plo[r2*68 + col] = lv;
        }
        ps1 += __shfl_xor_sync(0xffffffffu, ps1, 1);
        ps1 += __shfl_xor_sync(0xffffffffu, ps1, 2);
        ps2 += __shfl_xor_sync(0xffffffffu, ps2, 1);
        ps2 += __shfl_xor_sync(0xffffffffu, ps2, 2);
        if (tig == 0) { Sp[r1*4 + nq] = ps1; Sp[r2*4 + nq] = ps2; }

        oacc[0][0] *= f1; oacc[0][1] *= f1; oacc[1][0] *= f1; oacc[1][1] *= f1;
        oacc[0][2] *= f2; oacc[0][3] *= f2; oacc[1][2] *= f2; oacc[1][3] *= f2;
        mrun1 = mnew1; mrun2 = mnew2;
        __syncthreads();

        float4 s4a = *(const float4*)&Sp[r1*4];
        float4 s4b = *(const float4*)&Sp[r2*4];
        srun1 = srun1*f1 + (s4a.x + s4a.y + s4a.z + s4a.w);
        srun2 = srun2*f2 + (s4b.x + s4b.y + s4b.z + s4b.w);

        #pragma unroll
        for (int kc = 0; kc < 8; ++kc) {
            int pa1 = r1*68 + kc*8 + tig;
            int pa2 = r2*68 + kc*8 + tig;
            uint32_t ah0 = __float_as_uint(Phi[pa1]);
            uint32_t ah1 = __float_as_uint(Phi[pa2]);
            uint32_t ah2 = __float_as_uint(Phi[pa1 + 4]);
            uint32_t ah3 = __float_as_uint(Phi[pa2 + 4]);
            uint32_t al0 = __float_as_uint(Plo[pa1]);
            uint32_t al1 = __float_as_uint(Plo[pa2]);
            uint32_t al2 = __float_as_uint(Plo[pa1 + 4]);
            uint32_t al3 = __float_as_uint(Plo[pa2 + 4]);
            #pragma unroll
            for (int j = 0; j < 2; ++j) {
                int n0 = (nq*2 + j)*8;
                int vb0 = (kc*8 + tig    )*72 + n0 + gid;
                int vb1 = (kc*8 + tig + 4)*72 + n0 + gid;
                uint32_t bh0 = __float_as_uint(Vhi[vb0]);
                uint32_t bh1 = __float_as_uint(Vhi[vb1]);
                uint32_t bl0 = __float_as_uint(Vlo[vb0]);
                uint32_t bl1 = __float_as_uint(Vlo[vb1]);
                MMA_TF32(oacc[j], ah0, ah1, ah2, ah3, bl0, bl1);
                MMA_TF32(oacc[j], al0, al1, al2, al3, bh0, bh1);
                MMA_TF32(oacc[j], ah0, ah1, ah2, ah3, bh0, bh1);
            }
        }
    }

    float inv1 = 1.0f / srun1;
    float inv2 = 1.0f / srun2;
    #pragma unroll
    for (int j = 0; j < 2; ++j) {
        int col = (nq*2 + j)*8 + 2*tig;
        float2 o1; o1.x = oacc[j][0]*inv1; o1.y = oacc[j][1]*inv1;
        float2 o2; o2.x = oacc[j][2]*inv2; o2.y = oacc[j][3]*inv2;
        *(float2*)&Og[(size_t)(b*Tc + q0 + r1)*Dc + h*HDc + col] = o1;
        *(float2*)&Og[(size_t)(b*Tc + q0 + r2)*Dc + h*HDc + col] = o2;
    }
}

// ---------------- residual add + LayerNorm v2: warp-per-token ----------------
// grid Mc/8, block 256 (8 warps). Lane holds 16 values in registers; shfl-only
// reduction; no smem, no block barrier, single global read/write pass.
__global__ __launch_bounds__(256)
void add_ln_kernel(float* __restrict__ x, const float* __restrict__ r,
                   const float* __restrict__ g, const float* __restrict__ be)
{
    int w = threadIdx.x >> 5;
    int lane = threadIdx.x & 31;
    size_t tok = (size_t)blockIdx.x*8 + w;
    float* xr = x + tok*Dc;
    const float* rr = r + tok*Dc;

    float4 v[4];
    float s = 0.f, s2 = 0.f;
    #pragma unroll
    for (int i = 0; i < 4; ++i) {
        int c = (lane + i*32)*4;
        float4 xv = *(const float4*)&xr[c];
        float4 rv = *(const float4*)&rr[c];
        xv.x += rv.x; xv.y += rv.y; xv.z += rv.z; xv.w += rv.w;
        v[i] = xv;
        s  += xv.x + xv.y + xv.z + xv.w;
        s2 += xv.x*xv.x + xv.y*xv.y + xv.z*xv.z + xv.w*xv.w;
    }
    #pragma unroll
    for (int o = 16; o; o >>= 1) {
        s  += __shfl_xor_sync(0xffffffffu, s,  o);
        s2 += __shfl_xor_sync(0xffffffffu, s2, o);
    }
    float mu  = s * (1.0f/512.0f);
    float var = s2 * (1.0f/512.0f) - mu*mu;
    float rs  = rsqrtf(var + 1e-5f);
    #pragma unroll
    for (int i = 0; i < 4; ++i) {
        int c = (lane + i*32)*4;
        float4 gv = *(const float4*)&g[c];
        float4 bv = *(const float4*)&be[c];
        float4 y;
        y.x = (v[i].x - mu)*rs*gv.x + bv.x;
        y.y = (v[i].y - mu)*rs*gv.y + bv.y;
        y.z = (v[i].z - mu)*rs*gv.z + bv.z;
        y.w = (v[i].w - mu)*rs*gv.w + bv.w;
        *(float4*)&xr[c] = y;
    }
}

// ---------------- output head: out[b] = x[b, T-1] @ Wout + bout -------------
__global__ __launch_bounds__(512)
void out_kernel(const float* __restrict__ x, const float* __restrict__ Wout,
                const float* __restrict__ bout, float* __restrict__ out)
{
    int b = blockIdx.x;
    int n = threadIdx.x;
    __shared__ float xs[512];
    xs[n] = x[(size_t)(b*Tc + Tc - 1)*Dc + n];
    __syncthreads();
    float acc = bout[n];
    #pragma unroll 8
    for (int d = 0; d < Dc; ++d)
        acc += xs[d] * Wout[(size_t)d*Dc + n];
    out[b*Dc + n] = acc;
}

// ---------------- launcher ---------------------------------------------------
extern "C" void kernel_launch(void* const* d_in, const int* in_sizes, int n_in,
                              void* d_out, int out_size)
{
    const float* runs    = (const float*)d_in[0];
    const float* wickets = (const float*)d_in[1];
    const float* overs   = (const float*)d_in[2];
    const int*   batters = (const int*)  d_in[3];
    const int*   bowlers = (const int*)  d_in[4];
    const float* pemb    = (const float*)d_in[5];
    const float* Wf      = (const float*)d_in[6];
    const float* bf      = (const float*)d_in[7];
    const float* qtok    = (const float*)d_in[8];
    const float* Wq      = (const float*)d_in[9];
    const float* bq      = (const float*)d_in[10];
    const float* Wk      = (const float*)d_in[11];
    const float* bk      = (const float*)d_in[12];
    const float* Wv      = (const float*)d_in[13];
    const float* bv      = (const float*)d_in[14];
    const float* Wo      = (const float*)d_in[15];
    const float* bo      = (const float*)d_in[16];
    const float* rec_s   = (const float*)d_in[17];
    const float* bow_s   = (const float*)d_in[18];
    const float* bat_s   = (const float*)d_in[19];
    const float* W1      = (const float*)d_in[20];
    const float* b1      = (const float*)d_in[21];
    const float* W2      = (const float*)d_in[22];
    const float* b2      = (const float*)d_in[23];
    const float* g1      = (const float*)d_in[24];
    const float* be1     = (const float*)d_in[25];
    const float* g2      = (const float*)d_in[26];
    const float* be2     = (const float*)d_in[27];
    const float* Wout    = (const float*)d_in[28];
    const float* bout    = (const float*)d_in[29];
    float* out = (float*)d_out;

    float *x_, *att_, *tmp_, *ff_, *wqkv_, *bqkv_;
    cudaGetSymbolAddress((void**)&x_,    g_x);
    cudaGetSymbolAddress((void**)&att_,  g_att);
    cudaGetSymbolAddress((void**)&tmp_,  g_tmp);
    cudaGetSymbolAddress((void**)&ff_,   g_ff);
    cudaGetSymbolAddress((void**)&wqkv_, g_wqkv);
    cudaGetSymbolAddress((void**)&bqkv_, g_bqkv);

    cudaFuncSetAttribute(attn6_kernel,
                         cudaFuncAttributeMaxDynamicSharedMemorySize, ATTN6_SMEM);
    cudaFuncSetAttribute(tgemm_kernel<0>,
                         cudaFuncAttributeMaxDynamicSharedMemorySize, TGEMM_SMEM);
    cudaFuncSetAttribute(tgemm_kernel<1>,
                         cudaFuncAttributeMaxDynamicSharedMemorySize, TGEMM_SMEM);

    pack_qkv_kernel<<<Lc*Dc, 512>>>(Wq, Wk, Wv, wqkv_);
    pack_bqkv_kernel<<<Lc, 512>>>(bq, bk, bv, bqkv_);

    embed_kernel<<<Bc*Tc, 512>>>(runs, wickets, overs, batters, bowlers,
                                 pemb, Wf, bf, qtok, x_);

    dim3 g512 (Dc/TBN,   Mc/TBM);   // (4, 128)
    dim3 gQKV (QP/TBN,   Mc/TBM);   // (12, 128)
    dim3 g2048(DFFc/TBN, Mc/TBM);   // (16, 128)
    dim3 gattn(16, Hc, Bc);

    for (int l = 0; l < Lc; ++l) {
        tgemm_kernel<0><<<gQKV, 256, TGEMM_SMEM>>>(x_, wqkv_ + (size_t)l*Dc*QP,
                                                   bqkv_ + l*QP, ff_, Mc, QP, Dc);

        attn6_kernel<<<gattn, 256, ATTN6_SMEM>>>(ff_, batters, bowlers,
                                                 rec_s, bow_s, bat_s, l, att_);

        tgemm_kernel<0><<<g512, 256, TGEMM_SMEM>>>(att_, Wo + (size_t)l*Dc*Dc,
                                                   bo + l*Dc, tmp_, Mc, Dc, Dc);
        add_ln_kernel<<<Mc/8, 256>>>(x_, tmp_, g1 + l*Dc, be1 + l*Dc);

        tgemm_kernel<1><<<g2048, 256, TGEMM_SMEM>>>(x_, W1 + (size_t)l*Dc*DFFc,
                                                    b1 + l*DFFc, ff_, Mc, DFFc, Dc);
        tgemm_kernel<0><<<g512, 256, TGEMM_SMEM>>>(ff_, W2 + (size_t)l*DFFc*Dc,
                                                   b2 + l*Dc, tmp_, Mc, Dc, DFFc);
        add_ln_kernel<<<Mc/8, 256>>>(x_, tmp_, g2 + l*Dc, be2 + l*Dc);
    }

    out_kernel<<<Bc, 512>>>(x_, Wout, bout, out);
}